// round 11
// baseline (speedup 1.0000x reference)
#include <cuda_runtime.h>
#include <cuda_fp16.h>
#include <math.h>
#include <stdint.h>

#define LYRS 2
#define H 16
#define D 1024
#define DH 64
#define FF 4096
#define V 32000
#define SLEN 1024
#define BS 2
#define TOK (BS*SLEN)
#define EPS 1e-12f
#define K3D (3*D)
#define NSTG 3

// ---------------- scratch ----------------
__device__ float g_h  [TOK*D];
__device__ float g_qkv[TOK*K3D];
__device__ float g_tmp[TOK*D];
__device__ float g_bqkv[LYRS*K3D];
// fp16 operand buffers, tiled layout [rowTile128][kChunk64][128x64 swizzled 16KB]
// A-side buffers hold [hi|lo] (2K extent); weight buffers hold single fp16 (K extent)
__device__ __align__(256) __half g_a3 [TOK*2*D];
__device__ __align__(256) __half g_s2 [TOK*2*FF];
__device__ __align__(256) __half g_wqkv[LYRS*(size_t)K3D*D];
__device__ __align__(256) __half g_wo  [LYRS*(size_t)D*D];
__device__ __align__(256) __half g_w1  [LYRS*(size_t)FF*D];
__device__ __align__(256) __half g_w2  [LYRS*(size_t)D*FF];
__device__ __align__(256) __half g_wp  [(size_t)V*D];

// ---------------- helpers ----------------
__device__ __forceinline__ uint32_t s2u(const void* p) {
    uint32_t a;
    asm("{ .reg .u64 t; cvta.to.shared.u64 t, %1; cvt.u32.u64 %0, t; }" : "=r"(a) : "l"(p));
    return a;
}
#define SWZ(o) ((o) ^ (((o) >> 3) & 0x70))
__device__ __forceinline__ void mbar_init(uint32_t a, uint32_t c) {
    asm volatile("mbarrier.init.shared.b64 [%0], %1;" :: "r"(a), "r"(c) : "memory");
}
__device__ __forceinline__ void mbar_expect(uint32_t a, uint32_t tx) {
    asm volatile("mbarrier.arrive.expect_tx.shared.b64 _, [%0], %1;" :: "r"(a), "r"(tx) : "memory");
}
__device__ __forceinline__ void mbar_wait(uint32_t a, uint32_t ph) {
    asm volatile(
        "{\n\t.reg .pred P;\n\tL_%=:\n\t"
        "mbarrier.try_wait.parity.acquire.cta.shared::cta.b64 P, [%0], %1, 0x989680;\n\t"
        "@P bra D_%=;\n\tbra L_%=;\n\tD_%=:\n\t}" :: "r"(a), "r"(ph) : "memory");
}
__device__ __forceinline__ void bulk_ld(uint32_t dst, const void* src, uint32_t bytes, uint32_t mbar) {
    asm volatile("cp.async.bulk.shared::cta.global.mbarrier::complete_tx::bytes [%0], [%1], %2, [%3];"
                 :: "r"(dst), "l"(src), "r"(bytes), "r"(mbar) : "memory");
}
__device__ __forceinline__ void ldm4(uint32_t (&r)[4], uint32_t addr) {
    asm volatile("ldmatrix.sync.aligned.m8n8.x4.shared.b16 {%0,%1,%2,%3}, [%4];"
                 : "=r"(r[0]), "=r"(r[1]), "=r"(r[2]), "=r"(r[3]) : "r"(addr));
}
__device__ __forceinline__ void mma16816(float (&c)[4], const uint32_t a0, const uint32_t a1,
                                         const uint32_t a2, const uint32_t a3,
                                         const uint32_t b0, const uint32_t b1) {
    asm volatile("mma.sync.aligned.m16n8k16.row.col.f32.f16.f16.f32 "
                 "{%0,%1,%2,%3}, {%4,%5,%6,%7}, {%8,%9}, {%0,%1,%2,%3};"
                 : "+f"(c[0]), "+f"(c[1]), "+f"(c[2]), "+f"(c[3])
                 : "r"(a0), "r"(a1), "r"(a2), "r"(a3), "r"(b0), "r"(b1));
}
__device__ __forceinline__ void split2(float v, __half& hi, __half& lo) {
    hi = __float2half(v);
    lo = __float2half(v - __half2float(hi));
}
// store one fp16 element into tiled+swizzled layout; nch = total 64-col chunks of buffer
__device__ __forceinline__ void store_elem(__half* buf, int nch, int row, int k, __half v) {
    int t = row >> 7, rr = row & 127, c = k >> 6, kk = k & 63;
    uint32_t off = SWZ((uint32_t)(rr * 128 + kk * 2));
    *(__half*)((char*)buf + (((size_t)(t * nch + c)) << 14) + off) = v;
}

// ---------------- weight conversion: W[K,N] f32 -> tiled fp16 rows ----------------
__global__ void convert_w(const float* __restrict__ W, __half* __restrict__ out,
                          int K, int N, int rowOff) {
    __shared__ float t[32][33];
    int k0 = blockIdx.x * 32, n0 = blockIdx.y * 32;
    int tx = threadIdx.x & 31, ty = threadIdx.x >> 5;
    int nch = K >> 6;
    #pragma unroll
    for (int i = 0; i < 4; i++)
        t[ty + i * 8][tx] = W[(size_t)(k0 + ty + i * 8) * N + n0 + tx];
    __syncthreads();
    #pragma unroll
    for (int i = 0; i < 4; i++) {
        int n = rowOff + n0 + ty + i * 8, k = k0 + tx;
        store_elem(out, nch, n, k, __float2half(t[tx][ty + i * 8]));
    }
}
// fused QKV: blockIdx.z selects Wq/Wk/Wv, rowOff = z*D
__global__ void convert_qkv(const float* __restrict__ Wq, const float* __restrict__ Wk,
                            const float* __restrict__ Wv, __half* __restrict__ out) {
    __shared__ float t[32][33];
    const float* W = (blockIdx.z == 0) ? Wq : (blockIdx.z == 1) ? Wk : Wv;
    int k0 = blockIdx.x * 32, n0 = blockIdx.y * 32;
    int tx = threadIdx.x & 31, ty = threadIdx.x >> 5;
    #pragma unroll
    for (int i = 0; i < 4; i++)
        t[ty + i * 8][tx] = W[(size_t)(k0 + ty + i * 8) * D + n0 + tx];
    __syncthreads();
    #pragma unroll
    for (int i = 0; i < 4; i++) {
        int n = blockIdx.z * D + n0 + ty + i * 8, k = k0 + tx;
        store_elem(out, D >> 6, n, k, __float2half(t[tx][ty + i * 8]));
    }
}
__global__ void concat_bias(const float* __restrict__ a, const float* __restrict__ b,
                            const float* __restrict__ c, float* __restrict__ o) {
    int i = blockIdx.x * 256 + threadIdx.x;
    if (i < D) { o[i] = a[i]; o[D + i] = b[i]; o[2 * D + i] = c[i]; }
}

// ---------------- GEMM: C[2048,N] = A @ B^T, fp16 2-phase (A=[hi|lo], B=fp16) ----
// Stage = [A_hi 16K][A_lo 16K][B NB*16K]; B loaded once per k-chunk, reused by both phases.
// Threads 256*NB = 4 M-warps (32 rows) x 2NB N-warps (64 cols). Warp tile 32x64.
template<int NB>
__global__ void __launch_bounds__(256*NB, 1) gemm_kernel(
    const __half* __restrict__ A, const __half* __restrict__ B,
    const float* __restrict__ bias, float* __restrict__ C, __half* __restrict__ S,
    int Kp, int N, int act)
{
    constexpr int STG = (2 + NB) * 16384;
    extern __shared__ __align__(128) char smem[];
    const int tid = threadIdx.x, wid = tid >> 5, lane = tid & 31;
    const int wm = wid & 3, wn = wid >> 2;
    const int m0 = blockIdx.x * 128, n0 = blockIdx.y * NB * 128;
    const uint32_t sb = s2u(smem);
    const uint32_t MB = sb + NSTG * STG;
    const int nch0 = Kp / 64;

    if (tid == 0) {
        #pragma unroll
        for (int s = 0; s < NSTG; s++) mbar_init(MB + 8 * s, 1);
    }
    __syncthreads();

    auto issue = [&](int kk) {
        int s = kk % NSTG;
        uint32_t mb = MB + 8 * s, dst = sb + s * STG;
        mbar_expect(mb, (2 + NB) * 16384);
        bulk_ld(dst, (const char*)A + (((size_t)(blockIdx.x * 2 * nch0 + kk)) << 14), 16384, mb);
        bulk_ld(dst + 16384, (const char*)A + (((size_t)(blockIdx.x * 2 * nch0 + nch0 + kk)) << 14), 16384, mb);
        #pragma unroll
        for (int t = 0; t < NB; t++)
            bulk_ld(dst + 32768 + t * 16384,
                    (const char*)B + (((size_t)((blockIdx.y * NB + t) * nch0 + kk)) << 14), 16384, mb);
    };
    if (tid == 0) { issue(0); issue(1); issue(2); }

    float acc[2][8][4];
    #pragma unroll
    for (int mi = 0; mi < 2; mi++)
        #pragma unroll
        for (int ni = 0; ni < 8; ni++)
            #pragma unroll
            for (int j = 0; j < 4; j++) acc[mi][ni][j] = 0.f;

    const int lq = lane & 7, lh = (lane >> 3) & 1, lk = lane >> 4;

    for (int kk = 0; kk < nch0; kk++) {
        mbar_wait(MB + 8 * (kk % NSTG), (kk / NSTG) & 1);
        uint32_t stg = sb + (kk % NSTG) * STG;
        uint32_t bstg = stg + 32768 + (wn >> 1) * 16384;
        #pragma unroll
        for (int p = 0; p < 2; p++) {
            uint32_t astg = stg + p * 16384;
            #pragma unroll
            for (int ks = 0; ks < 4; ks++) {
                uint32_t af[2][4], bf[4][4];
                #pragma unroll
                for (int mt = 0; mt < 2; mt++) {
                    int r = wm * 32 + mt * 16 + lh * 8 + lq;
                    ldm4(af[mt], astg + r * 128 + (((ks * 2 + lk) ^ (r & 7)) << 4));
                }
                #pragma unroll
                for (int nt = 0; nt < 4; nt++) {
                    int r = (wn & 1) * 64 + nt * 16 + lh * 8 + lq;
                    ldm4(bf[nt], bstg + r * 128 + (((ks * 2 + lk) ^ (r & 7)) << 4));
                }
                #pragma unroll
                for (int mi = 0; mi < 2; mi++)
                    #pragma unroll
                    for (int ni = 0; ni < 8; ni++) {
                        uint32_t b0 = bf[ni >> 1][ni & 1], b1 = bf[ni >> 1][(ni & 1) + 2];
                        mma16816(acc[mi][ni], af[mi][0], af[mi][1], af[mi][2], af[mi][3], b0, b1);
                    }
            }
        }
        __syncthreads();
        if (tid == 0 && kk + NSTG < nch0) issue(kk + NSTG);
    }

    const int r0 = lane >> 2, cp = (lane & 3) * 2;
    const int nchS = N >> 5;
    #pragma unroll
    for (int mi = 0; mi < 2; mi++) {
        #pragma unroll
        for (int ni = 0; ni < 8; ni++) {
            int col = n0 + wn * 64 + ni * 8 + cp;
            float bb0 = bias[col], bb1 = bias[col + 1];
            #pragma unroll
            for (int half = 0; half < 2; half++) {
                int row = m0 + wm * 32 + mi * 16 + r0 + half * 8;
                float v0 = acc[mi][ni][half * 2 + 0] + bb0;
                float v1 = acc[mi][ni][half * 2 + 1] + bb1;
                if (act) {
                    v0 = 0.5f * v0 * (1.0f + erff(v0 * 0.70710678118654752f));
                    v1 = 0.5f * v1 * (1.0f + erff(v1 * 0.70710678118654752f));
                }
                if (C) {
                    float2 o; o.x = v0; o.y = v1;
                    *(float2*)(C + (size_t)row * N + col) = o;
                }
                if (S) {
                    __half h0, l0, h1, l1;
                    split2(v0, h0, l0); split2(v1, h1, l1);
                    int t = row >> 7, rr = row & 127;
                    uint32_t offh = SWZ((uint32_t)(rr * 128 + (col & 63) * 2));
                    __half2 hp; hp.x = h0; hp.y = h1;
                    *(__half2*)((char*)S + (((size_t)(t * nchS + (col >> 6))) << 14) + offh) = hp;
                    __half2 lp; lp.x = l0; lp.y = l1;
                    *(__half2*)((char*)S + (((size_t)(t * nchS + ((N + col) >> 6))) << 14) + offh) = lp;
                }
            }
        }
    }
}

// ---------------- LayerNorm ----------------
__device__ __forceinline__ float brsum(float v, float* sbuf) {
    int tid = threadIdx.x;
    #pragma unroll
    for (int o = 16; o; o >>= 1) v += __shfl_down_sync(0xffffffffu, v, o);
    if ((tid & 31) == 0) sbuf[tid >> 5] = v;
    __syncthreads();
    if (tid < 8) {
        v = sbuf[tid];
        #pragma unroll
        for (int o = 4; o; o >>= 1) v += __shfl_down_sync(0xffu, v, o);
        if (tid == 0) sbuf[0] = v;
    }
    __syncthreads();
    float r = sbuf[0];
    __syncthreads();
    return r;
}
__global__ void embed_ln_kernel(const int* __restrict__ x, const int* __restrict__ len,
                                const float* __restrict__ tok, const float* __restrict__ pos,
                                const float* __restrict__ g, const float* __restrict__ b,
                                float* __restrict__ out, __half* __restrict__ sp) {
    int row = blockIdx.x, bi = row / SLEN, s = row % SLEN, token = x[row], tid = threadIdx.x;
    __shared__ float buf[D]; __shared__ float red[8];
    float ls = 0.f;
    #pragma unroll
    for (int i = 0; i < 4; i++) {
        int c = tid + i * 256;
        float v = tok[(size_t)token * D + c] + pos[(size_t)s * D + c];
        buf[c] = v; ls += v;
    }
    float mean = brsum(ls, red) * (1.0f / D), ss = 0.f;
    #pragma unroll
    for (int i = 0; i < 4; i++) { float d = buf[tid + i * 256] - mean; ss += d * d; }
    float rstd = rsqrtf(brsum(ss, red) * (1.0f / D) + EPS);
    float mask = (s < len[bi]) ? 1.0f : 0.0f;
    #pragma unroll
    for (int i = 0; i < 4; i++) {
        int c = tid + i * 256;
        float v = (g[c] * (buf[c] - mean) * rstd + b[c]) * mask;
        out[(size_t)row * D + c] = v;
        __half hi, lo; split2(v, hi, lo);
        store_elem(sp, 32, row, c, hi);
        store_elem(sp, 32, row, D + c, lo);
    }
}
__global__ void add_ln_kernel(const float* __restrict__ a, const float* __restrict__ dl,
                              const float* __restrict__ g, const float* __restrict__ b,
                              const int* __restrict__ len, float* __restrict__ out,
                              __half* __restrict__ sp) {
    int row = blockIdx.x, bi = row / SLEN, s = row % SLEN, tid = threadIdx.x;
    __shared__ float buf[D]; __shared__ float red[8];
    float ls = 0.f;
    #pragma unroll
    for (int i = 0; i < 4; i++) {
        int c = tid + i * 256;
        float v = a[(size_t)row * D + c] + dl[(size_t)row * D + c];
        buf[c] = v; ls += v;
    }
    float mean = brsum(ls, red) * (1.0f / D), ss = 0.f;
    #pragma unroll
    for (int i = 0; i < 4; i++) { float d = buf[tid + i * 256] - mean; ss += d * d; }
    float rstd = rsqrtf(brsum(ss, red) * (1.0f / D) + EPS);
    float mask = len ? ((s < len[bi]) ? 1.0f : 0.0f) : 1.0f;
    #pragma unroll
    for (int i = 0; i < 4; i++) {
        int c = tid + i * 256;
        float v = (g[c] * (buf[c] - mean) * rstd + b[c]) * mask;
        out[(size_t)row * D + c] = v;
        __half hi, lo; split2(v, hi, lo);
        store_elem(sp, 32, row, c, hi);
        store_elem(sp, 32, row, D + c, lo);
    }
}

// ---------------- attention: 8 q/block, smem-staged K/V, warp softmax ----
#define QT 8
#define KCH 128
#define ATTN_SMEM ((QT*DH + QT*SLEN + KCH*65 + QT) * 4)
__global__ void attn_kernel(const float* __restrict__ qkv, __half* __restrict__ a3) {
    extern __shared__ float sm[];
    float* sq = sm;
    float* sc = sq + QT * DH;
    float* sk = sc + QT * SLEN;
    float* sinv = sk + KCH * 65;
    const int q0 = blockIdx.x * QT, hd = blockIdx.y, bb = blockIdx.z, tid = threadIdx.x;
    const int wid = tid >> 5, lane = tid & 31;
    const int nkb = q0 + QT;
    const size_t rb = (size_t)(bb * SLEN) * K3D + (size_t)hd * DH;

    for (int i = tid; i < QT * DH; i += 128)
        sq[i] = qkv[rb + (size_t)(q0 + i / DH) * K3D + (i % DH)] * 0.125f;
    __syncthreads();

    const float* kb = qkv + rb + D;
    for (int c0 = 0; c0 < nkb; c0 += KCH) {
        int rows = nkb - c0; if (rows > KCH) rows = KCH;
        for (int idx = tid; idx < rows * 16; idx += 128) {
            int r = idx >> 4, c4 = (idx & 15) * 4;
            float4 v = *(const float4*)(kb + (size_t)(c0 + r) * K3D + c4);
            sk[r * 65 + c4 + 0] = v.x; sk[r * 65 + c4 + 1] = v.y;
            sk[r * 65 + c4 + 2] = v.z; sk[r * 65 + c4 + 3] = v.w;
        }
        __syncthreads();
        for (int key = tid; key < rows; key += 128) {
            float a[QT];
            #pragma unroll
            for (int qi = 0; qi < QT; qi++) a[qi] = 0.f;
            #pragma unroll 8
            for (int d = 0; d < DH; d++) {
                float kd = sk[key * 65 + d];
                #pragma unroll
                for (int qi = 0; qi < QT; qi++) a[qi] = fmaf(sq[qi * DH + d], kd, a[qi]);
            }
            #pragma unroll
            for (int qi = 0; qi < QT; qi++) sc[qi * SLEN + c0 + key] = a[qi];
        }
        __syncthreads();
    }

    #pragma unroll
    for (int t = 0; t < 2; t++) {
        int qi = wid * 2 + t, bound = q0 + qi;
        float mx = -1e30f;
        for (int key = lane; key <= bound; key += 32) mx = fmaxf(mx, sc[qi * SLEN + key]);
        #pragma unroll
        for (int o = 16; o; o >>= 1) mx = fmaxf(mx, __shfl_xor_sync(0xffffffffu, mx, o));
        float s = 0.f;
        for (int key = lane; key < nkb; key += 32) {
            float e = (key <= bound) ? expf(sc[qi * SLEN + key] - mx) : 0.f;
            sc[qi * SLEN + key] = e; s += e;
        }
        #pragma unroll
        for (int o = 16; o; o >>= 1) s += __shfl_xor_sync(0xffffffffu, s, o);
        if (lane == 0) sinv[qi] = 1.0f / s;
    }
    __syncthreads();

    const int d = tid & 63, half = tid >> 6;
    const float* vb = qkv + rb + 2 * D;
    float a[QT];
    #pragma unroll
    for (int qi = 0; qi < QT; qi++) a[qi] = 0.f;
    for (int c0 = 0; c0 < nkb; c0 += KCH) {
        int rows = nkb - c0; if (rows > KCH) rows = KCH;
        for (int idx = tid; idx < rows * 16; idx += 128) {
            int r = idx >> 4, c4 = (idx & 15) * 4;
            float4 v = *(const float4*)(vb + (size_t)(c0 + r) * K3D + c4);
            sk[r * 65 + c4 + 0] = v.x; sk[r * 65 + c4 + 1] = v.y;
            sk[r * 65 + c4 + 2] = v.z; sk[r * 65 + c4 + 3] = v.w;
        }
        __syncthreads();
        for (int key = half; key < rows; key += 2) {
            float vv = sk[key * 65 + d];
            #pragma unroll
            for (int qi = 0; qi < QT; qi++)
                a[qi] = fmaf(sc[qi * SLEN + c0 + key], vv, a[qi]);
        }
        __syncthreads();
    }
    for (int qi = 0; qi < QT; qi++) {
        sk[tid] = a[qi]; __syncthreads();
        if (tid < 64) {
            float v = (sk[tid] + sk[tid + 64]) * sinv[qi];
            int row = bb * SLEN + q0 + qi;
            __half hi, lo; split2(v, hi, lo);
            store_elem(a3, 32, row, hd * DH + d, hi);
            store_elem(a3, 32, row, D + hd * DH + d, lo);
        }
        __syncthreads();
    }
}

// ---------------- launcher ----------------
extern "C" void kernel_launch(void* const* d_in, const int* in_sizes, int n_in,
                              void* d_out, int out_size) {
    const int*   x   = (const int*)  d_in[0];
    const int*   len = (const int*)  d_in[1];
    const float* tok = (const float*)d_in[2];
    const float* pos = (const float*)d_in[3];
    const float* leg = (const float*)d_in[4];
    const float* leb = (const float*)d_in[5];
    const float* Wq = (const float*)d_in[6];  const float* bq = (const float*)d_in[7];
    const float* Wk = (const float*)d_in[8];  const float* bk = (const float*)d_in[9];
    const float* Wv = (const float*)d_in[10]; const float* bv = (const float*)d_in[11];
    const float* Wo = (const float*)d_in[12]; const float* bo = (const float*)d_in[13];
    const float* l1g = (const float*)d_in[14]; const float* l1b = (const float*)d_in[15];
    const float* W1 = (const float*)d_in[16]; const float* b1 = (const float*)d_in[17];
    const float* W2 = (const float*)d_in[18]; const float* b2 = (const float*)d_in[19];
    const float* l2g = (const float*)d_in[20]; const float* l2b = (const float*)d_in[21];
    const float* pW = (const float*)d_in[22]; const float* pb = (const float*)d_in[23];
    float* out = (float*)d_out;

    float *h, *qkv, *tmp, *bqkv;
    __half *a3, *s2, *wqkv, *wo, *w1, *w2, *wp;
    cudaGetSymbolAddress((void**)&h, g_h);     cudaGetSymbolAddress((void**)&qkv, g_qkv);
    cudaGetSymbolAddress((void**)&tmp, g_tmp); cudaGetSymbolAddress((void**)&bqkv, g_bqkv);
    cudaGetSymbolAddress((void**)&a3, g_a3);   cudaGetSymbolAddress((void**)&s2, g_s2);
    cudaGetSymbolAddress((void**)&wqkv, g_wqkv); cudaGetSymbolAddress((void**)&wo, g_wo);
    cudaGetSymbolAddress((void**)&w1, g_w1);   cudaGetSymbolAddress((void**)&w2, g_w2);
    cudaGetSymbolAddress((void**)&wp, g_wp);

    const int sm1 = NSTG * 3 * 16384 + 64;   // NB=1
    const int sm2 = NSTG * 4 * 16384 + 64;   // NB=2
    cudaFuncSetAttribute(gemm_kernel<1>, cudaFuncAttributeMaxDynamicSharedMemorySize, sm1);
    cudaFuncSetAttribute(gemm_kernel<2>, cudaFuncAttributeMaxDynamicSharedMemorySize, sm2);
    cudaFuncSetAttribute(attn_kernel, cudaFuncAttributeMaxDynamicSharedMemorySize, ATTN_SMEM);

    // launch order chosen so index 3 (the ncu-captured launch) is the QKV GEMM
    embed_ln_kernel<<<TOK, 256>>>(x, len, tok, pos, leg, leb, h, a3);          // 0
    convert_qkv<<<dim3(D/32, D/32, 3), 256>>>(Wq, Wk, Wv, wqkv);               // 1
    concat_bias<<<4, 256>>>(bq, bk, bv, bqkv);                                 // 2
    gemm_kernel<2><<<dim3(TOK/128, K3D/256), 512, sm2>>>(                      // 3  <-- profiled
        a3, wqkv, bqkv, qkv, (__half*)0, D, K3D, 0);

    convert_w<<<dim3(D/32, D/32), 256>>>(Wo, wo, D, D, 0);
    convert_w<<<dim3(D/32, FF/32), 256>>>(W1, w1, D, FF, 0);
    convert_w<<<dim3(FF/32, D/32), 256>>>(W2, w2, FF, D, 0);
    {
        size_t w = (size_t)D * D;
        convert_qkv<<<dim3(D/32, D/32, 3), 256>>>(Wq + w, Wk + w, Wv + w, wqkv + (size_t)K3D * D);
        convert_w<<<dim3(D/32, D/32), 256>>>(Wo + w, wo + (size_t)D*D, D, D, 0);
        convert_w<<<dim3(D/32, FF/32), 256>>>(W1 + (size_t)D*FF, w1 + (size_t)FF*D, D, FF, 0);
        convert_w<<<dim3(FF/32, D/32), 256>>>(W2 + (size_t)FF*D, w2 + (size_t)D*FF, FF, D, 0);
        concat_bias<<<4, 256>>>(bq + D, bk + D, bv + D, bqkv + K3D);
    }
    convert_w<<<dim3(D/32, V/32), 256>>>(pW, wp, D, V, 0);

    for (int i = 0; i < LYRS; i++) {
        if (i > 0)
            gemm_kernel<2><<<dim3(TOK/128, K3D/256), 512, sm2>>>(
                a3, wqkv + (size_t)i*K3D*D, bqkv + (size_t)i*K3D, qkv, (__half*)0, D, K3D, 0);

        attn_kernel<<<dim3(SLEN/QT, H, BS), 128, ATTN_SMEM>>>(qkv, a3);

        gemm_kernel<1><<<dim3(TOK/128, D/128), 256, sm1>>>(
            a3, wo + (size_t)i*D*D, bo + (size_t)i*D, tmp, (__half*)0, D, D, 0);
        add_ln_kernel<<<TOK, 256>>>(h, tmp, l1g + (size_t)i*D, l1b + (size_t)i*D, (const int*)0, h, a3);

        gemm_kernel<2><<<dim3(TOK/128, FF/256), 512, sm2>>>(
            a3, w1 + (size_t)i*FF*D, b1 + (size_t)i*FF, (float*)0, s2, D, FF, 1);

        gemm_kernel<1><<<dim3(TOK/128, D/128), 256, sm1>>>(
            s2, w2 + (size_t)i*D*FF, b2 + (size_t)i*D, tmp, (__half*)0, FF, D, 0);
        add_ln_kernel<<<TOK, 256>>>(h, tmp, l2g + (size_t)i*D, l2b + (size_t)i*D, len, h, a3);
    }

    gemm_kernel<2><<<dim3(TOK/128, V/256), 512, sm2>>>(
        a3, wp, pb, out, (__half*)0, D, V, 0);
}

// round 12
// speedup vs baseline: 1.0477x; 1.0477x over previous
#include <cuda_runtime.h>
#include <cuda_fp16.h>
#include <math.h>
#include <stdint.h>

#define LYRS 2
#define H 16
#define D 1024
#define DH 64
#define FF 4096
#define V 32000
#define SLEN 1024
#define BS 2
#define TOK (BS*SLEN)
#define EPS 1e-12f
#define K3D (3*D)
#define NSTG 2
#define STG (3*16384)

// ---------------- scratch ----------------
__device__ float g_h  [TOK*D];
__device__ float g_qkv[TOK*K3D];
__device__ float g_tmp[TOK*D];
__device__ float g_bqkv[LYRS*K3D];
// fp16 operand buffers, tiled layout [rowTile128][kChunk64][128x64 swizzled 16KB]
// A-side buffers hold [hi|lo] (2K extent); weight buffers hold single fp16 (K extent)
__device__ __align__(256) __half g_a3 [TOK*2*D];
__device__ __align__(256) __half g_s2 [TOK*2*FF];
__device__ __align__(256) __half g_wqkv[LYRS*(size_t)K3D*D];
__device__ __align__(256) __half g_wo  [LYRS*(size_t)D*D];
__device__ __align__(256) __half g_w1  [LYRS*(size_t)FF*D];
__device__ __align__(256) __half g_w2  [LYRS*(size_t)D*FF];
__device__ __align__(256) __half g_wp  [(size_t)V*D];

// ---------------- helpers ----------------
__device__ __forceinline__ uint32_t s2u(const void* p) {
    uint32_t a;
    asm("{ .reg .u64 t; cvta.to.shared.u64 t, %1; cvt.u32.u64 %0, t; }" : "=r"(a) : "l"(p));
    return a;
}
#define SWZ(o) ((o) ^ (((o) >> 3) & 0x70))
__device__ __forceinline__ void mbar_init(uint32_t a, uint32_t c) {
    asm volatile("mbarrier.init.shared.b64 [%0], %1;" :: "r"(a), "r"(c) : "memory");
}
__device__ __forceinline__ void mbar_expect(uint32_t a, uint32_t tx) {
    asm volatile("mbarrier.arrive.expect_tx.shared.b64 _, [%0], %1;" :: "r"(a), "r"(tx) : "memory");
}
__device__ __forceinline__ void mbar_wait(uint32_t a, uint32_t ph) {
    asm volatile(
        "{\n\t.reg .pred P;\n\tL_%=:\n\t"
        "mbarrier.try_wait.parity.acquire.cta.shared::cta.b64 P, [%0], %1, 0x989680;\n\t"
        "@P bra D_%=;\n\tbra L_%=;\n\tD_%=:\n\t}" :: "r"(a), "r"(ph) : "memory");
}
__device__ __forceinline__ void bulk_ld(uint32_t dst, const void* src, uint32_t bytes, uint32_t mbar) {
    asm volatile("cp.async.bulk.shared::cta.global.mbarrier::complete_tx::bytes [%0], [%1], %2, [%3];"
                 :: "r"(dst), "l"(src), "r"(bytes), "r"(mbar) : "memory");
}
__device__ __forceinline__ void ldm4(uint32_t (&r)[4], uint32_t addr) {
    asm volatile("ldmatrix.sync.aligned.m8n8.x4.shared.b16 {%0,%1,%2,%3}, [%4];"
                 : "=r"(r[0]), "=r"(r[1]), "=r"(r[2]), "=r"(r[3]) : "r"(addr));
}
__device__ __forceinline__ void mma16816(float (&c)[4], const uint32_t a0, const uint32_t a1,
                                         const uint32_t a2, const uint32_t a3,
                                         const uint32_t b0, const uint32_t b1) {
    asm volatile("mma.sync.aligned.m16n8k16.row.col.f32.f16.f16.f32 "
                 "{%0,%1,%2,%3}, {%4,%5,%6,%7}, {%8,%9}, {%0,%1,%2,%3};"
                 : "+f"(c[0]), "+f"(c[1]), "+f"(c[2]), "+f"(c[3])
                 : "r"(a0), "r"(a1), "r"(a2), "r"(a3), "r"(b0), "r"(b1));
}
__device__ __forceinline__ void split2(float v, __half& hi, __half& lo) {
    hi = __float2half(v);
    lo = __float2half(v - __half2float(hi));
}
// store one fp16 element into tiled+swizzled layout; nch = total 64-col chunks of buffer
__device__ __forceinline__ void store_elem(__half* buf, int nch, int row, int k, __half v) {
    int t = row >> 7, rr = row & 127, c = k >> 6, kk = k & 63;
    uint32_t off = SWZ((uint32_t)(rr * 128 + kk * 2));
    *(__half*)((char*)buf + (((size_t)(t * nch + c)) << 14) + off) = v;
}

// ---------------- weight conversion: W[K,N] f32 -> tiled fp16 rows ----------------
__global__ void convert_w(const float* __restrict__ W, __half* __restrict__ out,
                          int K, int N, int rowOff) {
    __shared__ float t[32][33];
    int k0 = blockIdx.x * 32, n0 = blockIdx.y * 32;
    int tx = threadIdx.x & 31, ty = threadIdx.x >> 5;
    int nch = K >> 6;
    #pragma unroll
    for (int i = 0; i < 4; i++)
        t[ty + i * 8][tx] = W[(size_t)(k0 + ty + i * 8) * N + n0 + tx];
    __syncthreads();
    #pragma unroll
    for (int i = 0; i < 4; i++) {
        int n = rowOff + n0 + ty + i * 8, k = k0 + tx;
        store_elem(out, nch, n, k, __float2half(t[tx][ty + i * 8]));
    }
}
// fused QKV: blockIdx.z selects Wq/Wk/Wv, rowOff = z*D
__global__ void convert_qkv(const float* __restrict__ Wq, const float* __restrict__ Wk,
                            const float* __restrict__ Wv, __half* __restrict__ out) {
    __shared__ float t[32][33];
    const float* W = (blockIdx.z == 0) ? Wq : (blockIdx.z == 1) ? Wk : Wv;
    int k0 = blockIdx.x * 32, n0 = blockIdx.y * 32;
    int tx = threadIdx.x & 31, ty = threadIdx.x >> 5;
    #pragma unroll
    for (int i = 0; i < 4; i++)
        t[ty + i * 8][tx] = W[(size_t)(k0 + ty + i * 8) * D + n0 + tx];
    __syncthreads();
    #pragma unroll
    for (int i = 0; i < 4; i++) {
        int n = blockIdx.z * D + n0 + ty + i * 8, k = k0 + tx;
        store_elem(out, D >> 6, n, k, __float2half(t[tx][ty + i * 8]));
    }
}
__global__ void concat_bias(const float* __restrict__ a, const float* __restrict__ b,
                            const float* __restrict__ c, float* __restrict__ o) {
    int i = blockIdx.x * 256 + threadIdx.x;
    if (i < D) { o[i] = a[i]; o[D + i] = b[i]; o[2 * D + i] = c[i]; }
}

// ---------------- GEMM: C[2048,N] = A @ B^T, fp16 2-phase (A=[hi|lo], B=fp16) ----
// Tile 128x128, 8 warps (4M x 2N), warp tile 32x64. Stage=[A_hi|A_lo|B] 48KB, NSTG=2.
// 96 KB smem + <=128 regs -> 2 CTAs/SM for cross-CTA latency hiding.
__global__ void __launch_bounds__(256, 2) gemm_kernel(
    const __half* __restrict__ A, const __half* __restrict__ B,
    const float* __restrict__ bias, float* __restrict__ C, __half* __restrict__ S,
    int Kp, int N, int act)
{
    extern __shared__ __align__(128) char smem[];
    const int tid = threadIdx.x, wid = tid >> 5, lane = tid & 31;
    const int wm = wid & 3, wn = wid >> 2;
    const int m0 = blockIdx.x * 128, n0 = blockIdx.y * 128;
    const uint32_t sb = s2u(smem);
    const uint32_t MB = sb + NSTG * STG;
    const int nch0 = Kp / 64;

    if (tid == 0) {
        #pragma unroll
        for (int s = 0; s < NSTG; s++) mbar_init(MB + 8 * s, 1);
    }
    __syncthreads();

    auto issue = [&](int kk) {
        int s = kk & (NSTG - 1);
        uint32_t mb = MB + 8 * s, dst = sb + s * STG;
        mbar_expect(mb, 3 * 16384);
        bulk_ld(dst, (const char*)A + (((size_t)(blockIdx.x * 2 * nch0 + kk)) << 14), 16384, mb);
        bulk_ld(dst + 16384, (const char*)A + (((size_t)(blockIdx.x * 2 * nch0 + nch0 + kk)) << 14), 16384, mb);
        bulk_ld(dst + 32768, (const char*)B + (((size_t)(blockIdx.y * nch0 + kk)) << 14), 16384, mb);
    };
    if (tid == 0) { issue(0); issue(1); }

    float acc[2][8][4];
    #pragma unroll
    for (int mi = 0; mi < 2; mi++)
        #pragma unroll
        for (int ni = 0; ni < 8; ni++)
            #pragma unroll
            for (int j = 0; j < 4; j++) acc[mi][ni][j] = 0.f;

    const int lq = lane & 7, lh = (lane >> 3) & 1, lk = lane >> 4;

    for (int kk = 0; kk < nch0; kk++) {
        mbar_wait(MB + 8 * (kk & (NSTG - 1)), (kk >> 1) & 1);
        uint32_t stg = sb + (kk & (NSTG - 1)) * STG;
        uint32_t bstg = stg + 32768;
        #pragma unroll
        for (int p = 0; p < 2; p++) {
            uint32_t astg = stg + p * 16384;
            #pragma unroll
            for (int ks = 0; ks < 4; ks++) {
                uint32_t af[2][4], bf[4][4];
                #pragma unroll
                for (int mt = 0; mt < 2; mt++) {
                    int r = wm * 32 + mt * 16 + lh * 8 + lq;
                    ldm4(af[mt], astg + r * 128 + (((ks * 2 + lk) ^ (r & 7)) << 4));
                }
                #pragma unroll
                for (int nt = 0; nt < 4; nt++) {
                    int r = wn * 64 + nt * 16 + lh * 8 + lq;
                    ldm4(bf[nt], bstg + r * 128 + (((ks * 2 + lk) ^ (r & 7)) << 4));
                }
                #pragma unroll
                for (int mi = 0; mi < 2; mi++)
                    #pragma unroll
                    for (int ni = 0; ni < 8; ni++) {
                        uint32_t b0 = bf[ni >> 1][ni & 1], b1 = bf[ni >> 1][(ni & 1) + 2];
                        mma16816(acc[mi][ni], af[mi][0], af[mi][1], af[mi][2], af[mi][3], b0, b1);
                    }
            }
        }
        __syncthreads();
        if (tid == 0 && kk + NSTG < nch0) issue(kk + NSTG);
    }

    const int r0 = lane >> 2, cp = (lane & 3) * 2;
    const int nchS = N >> 5;
    #pragma unroll
    for (int mi = 0; mi < 2; mi++) {
        #pragma unroll
        for (int ni = 0; ni < 8; ni++) {
            int col = n0 + wn * 64 + ni * 8 + cp;
            float bb0 = bias[col], bb1 = bias[col + 1];
            #pragma unroll
            for (int half = 0; half < 2; half++) {
                int row = m0 + wm * 32 + mi * 16 + r0 + half * 8;
                float v0 = acc[mi][ni][half * 2 + 0] + bb0;
                float v1 = acc[mi][ni][half * 2 + 1] + bb1;
                if (act) {
                    v0 = 0.5f * v0 * (1.0f + erff(v0 * 0.70710678118654752f));
                    v1 = 0.5f * v1 * (1.0f + erff(v1 * 0.70710678118654752f));
                }
                if (C) {
                    float2 o; o.x = v0; o.y = v1;
                    *(float2*)(C + (size_t)row * N + col) = o;
                }
                if (S) {
                    __half h0, l0, h1, l1;
                    split2(v0, h0, l0); split2(v1, h1, l1);
                    int t = row >> 7, rr = row & 127;
                    uint32_t offh = SWZ((uint32_t)(rr * 128 + (col & 63) * 2));
                    __half2 hp; hp.x = h0; hp.y = h1;
                    *(__half2*)((char*)S + (((size_t)(t * nchS + (col >> 6))) << 14) + offh) = hp;
                    __half2 lp; lp.x = l0; lp.y = l1;
                    *(__half2*)((char*)S + (((size_t)(t * nchS + ((N + col) >> 6))) << 14) + offh) = lp;
                }
            }
        }
    }
}

// ---------------- LayerNorm ----------------
__device__ __forceinline__ float brsum(float v, float* sbuf) {
    int tid = threadIdx.x;
    #pragma unroll
    for (int o = 16; o; o >>= 1) v += __shfl_down_sync(0xffffffffu, v, o);
    if ((tid & 31) == 0) sbuf[tid >> 5] = v;
    __syncthreads();
    if (tid < 8) {
        v = sbuf[tid];
        #pragma unroll
        for (int o = 4; o; o >>= 1) v += __shfl_down_sync(0xffu, v, o);
        if (tid == 0) sbuf[0] = v;
    }
    __syncthreads();
    float r = sbuf[0];
    __syncthreads();
    return r;
}
__global__ void embed_ln_kernel(const int* __restrict__ x, const int* __restrict__ len,
                                const float* __restrict__ tok, const float* __restrict__ pos,
                                const float* __restrict__ g, const float* __restrict__ b,
                                float* __restrict__ out, __half* __restrict__ sp) {
    int row = blockIdx.x, bi = row / SLEN, s = row % SLEN, token = x[row], tid = threadIdx.x;
    __shared__ float buf[D]; __shared__ float red[8];
    float ls = 0.f;
    #pragma unroll
    for (int i = 0; i < 4; i++) {
        int c = tid + i * 256;
        float v = tok[(size_t)token * D + c] + pos[(size_t)s * D + c];
        buf[c] = v; ls += v;
    }
    float mean = brsum(ls, red) * (1.0f / D), ss = 0.f;
    #pragma unroll
    for (int i = 0; i < 4; i++) { float d = buf[tid + i * 256] - mean; ss += d * d; }
    float rstd = rsqrtf(brsum(ss, red) * (1.0f / D) + EPS);
    float mask = (s < len[bi]) ? 1.0f : 0.0f;
    #pragma unroll
    for (int i = 0; i < 4; i++) {
        int c = tid + i * 256;
        float v = (g[c] * (buf[c] - mean) * rstd + b[c]) * mask;
        out[(size_t)row * D + c] = v;
        __half hi, lo; split2(v, hi, lo);
        store_elem(sp, 32, row, c, hi);
        store_elem(sp, 32, row, D + c, lo);
    }
}
__global__ void add_ln_kernel(const float* __restrict__ a, const float* __restrict__ dl,
                              const float* __restrict__ g, const float* __restrict__ b,
                              const int* __restrict__ len, float* __restrict__ out,
                              __half* __restrict__ sp) {
    int row = blockIdx.x, bi = row / SLEN, s = row % SLEN, tid = threadIdx.x;
    __shared__ float buf[D]; __shared__ float red[8];
    float ls = 0.f;
    #pragma unroll
    for (int i = 0; i < 4; i++) {
        int c = tid + i * 256;
        float v = a[(size_t)row * D + c] + dl[(size_t)row * D + c];
        buf[c] = v; ls += v;
    }
    float mean = brsum(ls, red) * (1.0f / D), ss = 0.f;
    #pragma unroll
    for (int i = 0; i < 4; i++) { float d = buf[tid + i * 256] - mean; ss += d * d; }
    float rstd = rsqrtf(brsum(ss, red) * (1.0f / D) + EPS);
    float mask = len ? ((s < len[bi]) ? 1.0f : 0.0f) : 1.0f;
    #pragma unroll
    for (int i = 0; i < 4; i++) {
        int c = tid + i * 256;
        float v = (g[c] * (buf[c] - mean) * rstd + b[c]) * mask;
        out[(size_t)row * D + c] = v;
        __half hi, lo; split2(v, hi, lo);
        store_elem(sp, 32, row, c, hi);
        store_elem(sp, 32, row, D + c, lo);
    }
}

// ---------------- attention: 8 q/block, smem-staged K/V, warp softmax ----
#define QT 8
#define KCH 128
#define ATTN_SMEM ((QT*DH + QT*SLEN + KCH*65 + QT) * 4)
__global__ void attn_kernel(const float* __restrict__ qkv, __half* __restrict__ a3) {
    extern __shared__ float sm[];
    float* sq = sm;
    float* sc = sq + QT * DH;
    float* sk = sc + QT * SLEN;
    float* sinv = sk + KCH * 65;
    const int q0 = blockIdx.x * QT, hd = blockIdx.y, bb = blockIdx.z, tid = threadIdx.x;
    const int wid = tid >> 5, lane = tid & 31;
    const int nkb = q0 + QT;
    const size_t rb = (size_t)(bb * SLEN) * K3D + (size_t)hd * DH;

    for (int i = tid; i < QT * DH; i += 128)
        sq[i] = qkv[rb + (size_t)(q0 + i / DH) * K3D + (i % DH)] * 0.125f;
    __syncthreads();

    const float* kb = qkv + rb + D;
    for (int c0 = 0; c0 < nkb; c0 += KCH) {
        int rows = nkb - c0; if (rows > KCH) rows = KCH;
        for (int idx = tid; idx < rows * 16; idx += 128) {
            int r = idx >> 4, c4 = (idx & 15) * 4;
            float4 v = *(const float4*)(kb + (size_t)(c0 + r) * K3D + c4);
            sk[r * 65 + c4 + 0] = v.x; sk[r * 65 + c4 + 1] = v.y;
            sk[r * 65 + c4 + 2] = v.z; sk[r * 65 + c4 + 3] = v.w;
        }
        __syncthreads();
        for (int key = tid; key < rows; key += 128) {
            float a[QT];
            #pragma unroll
            for (int qi = 0; qi < QT; qi++) a[qi] = 0.f;
            #pragma unroll 8
            for (int d = 0; d < DH; d++) {
                float kd = sk[key * 65 + d];
                #pragma unroll
                for (int qi = 0; qi < QT; qi++) a[qi] = fmaf(sq[qi * DH + d], kd, a[qi]);
            }
            #pragma unroll
            for (int qi = 0; qi < QT; qi++) sc[qi * SLEN + c0 + key] = a[qi];
        }
        __syncthreads();
    }

    #pragma unroll
    for (int t = 0; t < 2; t++) {
        int qi = wid * 2 + t, bound = q0 + qi;
        float mx = -1e30f;
        for (int key = lane; key <= bound; key += 32) mx = fmaxf(mx, sc[qi * SLEN + key]);
        #pragma unroll
        for (int o = 16; o; o >>= 1) mx = fmaxf(mx, __shfl_xor_sync(0xffffffffu, mx, o));
        float s = 0.f;
        for (int key = lane; key < nkb; key += 32) {
            float e = (key <= bound) ? expf(sc[qi * SLEN + key] - mx) : 0.f;
            sc[qi * SLEN + key] = e; s += e;
        }
        #pragma unroll
        for (int o = 16; o; o >>= 1) s += __shfl_xor_sync(0xffffffffu, s, o);
        if (lane == 0) sinv[qi] = 1.0f / s;
    }
    __syncthreads();

    const int d = tid & 63, half = tid >> 6;
    const float* vb = qkv + rb + 2 * D;
    float a[QT];
    #pragma unroll
    for (int qi = 0; qi < QT; qi++) a[qi] = 0.f;
    for (int c0 = 0; c0 < nkb; c0 += KCH) {
        int rows = nkb - c0; if (rows > KCH) rows = KCH;
        for (int idx = tid; idx < rows * 16; idx += 128) {
            int r = idx >> 4, c4 = (idx & 15) * 4;
            float4 v = *(const float4*)(vb + (size_t)(c0 + r) * K3D + c4);
            sk[r * 65 + c4 + 0] = v.x; sk[r * 65 + c4 + 1] = v.y;
            sk[r * 65 + c4 + 2] = v.z; sk[r * 65 + c4 + 3] = v.w;
        }
        __syncthreads();
        for (int key = half; key < rows; key += 2) {
            float vv = sk[key * 65 + d];
            #pragma unroll
            for (int qi = 0; qi < QT; qi++)
                a[qi] = fmaf(sc[qi * SLEN + c0 + key], vv, a[qi]);
        }
        __syncthreads();
    }
    for (int qi = 0; qi < QT; qi++) {
        sk[tid] = a[qi]; __syncthreads();
        if (tid < 64) {
            float v = (sk[tid] + sk[tid + 64]) * sinv[qi];
            int row = bb * SLEN + q0 + qi;
            __half hi, lo; split2(v, hi, lo);
            store_elem(a3, 32, row, hd * DH + d, hi);
            store_elem(a3, 32, row, D + hd * DH + d, lo);
        }
        __syncthreads();
    }
}

// ---------------- launcher ----------------
extern "C" void kernel_launch(void* const* d_in, const int* in_sizes, int n_in,
                              void* d_out, int out_size) {
    const int*   x   = (const int*)  d_in[0];
    const int*   len = (const int*)  d_in[1];
    const float* tok = (const float*)d_in[2];
    const float* pos = (const float*)d_in[3];
    const float* leg = (const float*)d_in[4];
    const float* leb = (const float*)d_in[5];
    const float* Wq = (const float*)d_in[6];  const float* bq = (const float*)d_in[7];
    const float* Wk = (const float*)d_in[8];  const float* bk = (const float*)d_in[9];
    const float* Wv = (const float*)d_in[10]; const float* bv = (const float*)d_in[11];
    const float* Wo = (const float*)d_in[12]; const float* bo = (const float*)d_in[13];
    const float* l1g = (const float*)d_in[14]; const float* l1b = (const float*)d_in[15];
    const float* W1 = (const float*)d_in[16]; const float* b1 = (const float*)d_in[17];
    const float* W2 = (const float*)d_in[18]; const float* b2 = (const float*)d_in[19];
    const float* l2g = (const float*)d_in[20]; const float* l2b = (const float*)d_in[21];
    const float* pW = (const float*)d_in[22]; const float* pb = (const float*)d_in[23];
    float* out = (float*)d_out;

    float *h, *qkv, *tmp, *bqkv;
    __half *a3, *s2, *wqkv, *wo, *w1, *w2, *wp;
    cudaGetSymbolAddress((void**)&h, g_h);     cudaGetSymbolAddress((void**)&qkv, g_qkv);
    cudaGetSymbolAddress((void**)&tmp, g_tmp); cudaGetSymbolAddress((void**)&bqkv, g_bqkv);
    cudaGetSymbolAddress((void**)&a3, g_a3);   cudaGetSymbolAddress((void**)&s2, g_s2);
    cudaGetSymbolAddress((void**)&wqkv, g_wqkv); cudaGetSymbolAddress((void**)&wo, g_wo);
    cudaGetSymbolAddress((void**)&w1, g_w1);   cudaGetSymbolAddress((void**)&w2, g_w2);
    cudaGetSymbolAddress((void**)&wp, g_wp);

    const int smg = NSTG * STG + 64;   // 98368
    cudaFuncSetAttribute(gemm_kernel, cudaFuncAttributeMaxDynamicSharedMemorySize, smg);
    cudaFuncSetAttribute(attn_kernel, cudaFuncAttributeMaxDynamicSharedMemorySize, ATTN_SMEM);

    // launch order chosen so index 3 (the ncu-captured launch) is the QKV GEMM
    embed_ln_kernel<<<TOK, 256>>>(x, len, tok, pos, leg, leb, h, a3);          // 0
    convert_qkv<<<dim3(D/32, D/32, 3), 256>>>(Wq, Wk, Wv, wqkv);               // 1
    concat_bias<<<4, 256>>>(bq, bk, bv, bqkv);                                 // 2
    gemm_kernel<<<dim3(TOK/128, K3D/128), 256, smg>>>(                         // 3  <-- profiled
        a3, wqkv, bqkv, qkv, (__half*)0, D, K3D, 0);

    convert_w<<<dim3(D/32, D/32), 256>>>(Wo, wo, D, D, 0);
    convert_w<<<dim3(D/32, FF/32), 256>>>(W1, w1, D, FF, 0);
    convert_w<<<dim3(FF/32, D/32), 256>>>(W2, w2, FF, D, 0);
    {
        size_t w = (size_t)D * D;
        convert_qkv<<<dim3(D/32, D/32, 3), 256>>>(Wq + w, Wk + w, Wv + w, wqkv + (size_t)K3D * D);
        convert_w<<<dim3(D/32, D/32), 256>>>(Wo + w, wo + (size_t)D*D, D, D, 0);
        convert_w<<<dim3(D/32, FF/32), 256>>>(W1 + (size_t)D*FF, w1 + (size_t)FF*D, D, FF, 0);
        convert_w<<<dim3(FF/32, D/32), 256>>>(W2 + (size_t)FF*D, w2 + (size_t)D*FF, FF, D, 0);
        concat_bias<<<4, 256>>>(bq + D, bk + D, bv + D, bqkv + K3D);
    }
    convert_w<<<dim3(D/32, V/32), 256>>>(pW, wp, D, V, 0);

    for (int i = 0; i < LYRS; i++) {
        if (i > 0)
            gemm_kernel<<<dim3(TOK/128, K3D/128), 256, smg>>>(
                a3, wqkv + (size_t)i*K3D*D, bqkv + (size_t)i*K3D, qkv, (__half*)0, D, K3D, 0);

        attn_kernel<<<dim3(SLEN/QT, H, BS), 128, ATTN_SMEM>>>(qkv, a3);

        gemm_kernel<<<dim3(TOK/128, D/128), 256, smg>>>(
            a3, wo + (size_t)i*D*D, bo + (size_t)i*D, tmp, (__half*)0, D, D, 0);
        add_ln_kernel<<<TOK, 256>>>(h, tmp, l1g + (size_t)i*D, l1b + (size_t)i*D, (const int*)0, h, a3);

        gemm_kernel<<<dim3(TOK/128, FF/128), 256, smg>>>(
            a3, w1 + (size_t)i*FF*D, b1 + (size_t)i*FF, (float*)0, s2, D, FF, 1);

        gemm_kernel<<<dim3(TOK/128, D/128), 256, smg>>>(
            s2, w2 + (size_t)i*D*FF, b2 + (size_t)i*D, tmp, (__half*)0, FF, D, 0);
        add_ln_kernel<<<TOK, 256>>>(h, tmp, l2g + (size_t)i*D, l2b + (size_t)i*D, len, h, a3);
    }

    gemm_kernel<<<dim3(TOK/128, V/128), 256, smg>>>(
        a3, wp, pb, out, (__half*)0, D, V, 0);
}

// round 13
// speedup vs baseline: 1.0871x; 1.0376x over previous
#include <cuda_runtime.h>
#include <cuda_fp16.h>
#include <math.h>
#include <stdint.h>

#define LYRS 2
#define H 16
#define D 1024
#define DH 64
#define FF 4096
#define V 32000
#define SLEN 1024
#define BS 2
#define TOK (BS*SLEN)
#define EPS 1e-12f
#define K3D (3*D)
#define NSTG 4
#define STG (3*8192)

// ---------------- scratch ----------------
__device__ float g_h  [TOK*D];
__device__ float g_qkv[TOK*K3D];
__device__ float g_tmp[TOK*D];
__device__ float g_bqkv[LYRS*K3D];
// fp16 operand buffers, tiled layout [rowTile128][kChunk32][128x32 sw64-swizzled 8KB]
// A-side buffers hold [hi|lo] (2K extent); weight buffers hold single fp16 (K extent)
__device__ __align__(256) __half g_a3 [TOK*2*D];
__device__ __align__(256) __half g_s2 [TOK*2*FF];
__device__ __align__(256) __half g_wqkv[LYRS*(size_t)K3D*D];
__device__ __align__(256) __half g_wo  [LYRS*(size_t)D*D];
__device__ __align__(256) __half g_w1  [LYRS*(size_t)FF*D];
__device__ __align__(256) __half g_w2  [LYRS*(size_t)D*FF];
__device__ __align__(256) __half g_wp  [(size_t)V*D];

// ---------------- helpers ----------------
__device__ __forceinline__ uint32_t s2u(const void* p) {
    uint32_t a;
    asm("{ .reg .u64 t; cvta.to.shared.u64 t, %1; cvt.u32.u64 %0, t; }" : "=r"(a) : "l"(p));
    return a;
}
// SW64 swizzle for 64-byte rows (slot[5:4] ^= row bits [8:7])
#define SWZ32(o) ((o) ^ (((o) >> 3) & 0x30))
__device__ __forceinline__ void mbar_init(uint32_t a, uint32_t c) {
    asm volatile("mbarrier.init.shared.b64 [%0], %1;" :: "r"(a), "r"(c) : "memory");
}
__device__ __forceinline__ void mbar_expect(uint32_t a, uint32_t tx) {
    asm volatile("mbarrier.arrive.expect_tx.shared.b64 _, [%0], %1;" :: "r"(a), "r"(tx) : "memory");
}
__device__ __forceinline__ void mbar_wait(uint32_t a, uint32_t ph) {
    asm volatile(
        "{\n\t.reg .pred P;\n\tL_%=:\n\t"
        "mbarrier.try_wait.parity.acquire.cta.shared::cta.b64 P, [%0], %1, 0x989680;\n\t"
        "@P bra D_%=;\n\tbra L_%=;\n\tD_%=:\n\t}" :: "r"(a), "r"(ph) : "memory");
}
__device__ __forceinline__ void bulk_ld(uint32_t dst, const void* src, uint32_t bytes, uint32_t mbar) {
    asm volatile("cp.async.bulk.shared::cta.global.mbarrier::complete_tx::bytes [%0], [%1], %2, [%3];"
                 :: "r"(dst), "l"(src), "r"(bytes), "r"(mbar) : "memory");
}
__device__ __forceinline__ void ldm4(uint32_t (&r)[4], uint32_t addr) {
    asm volatile("ldmatrix.sync.aligned.m8n8.x4.shared.b16 {%0,%1,%2,%3}, [%4];"
                 : "=r"(r[0]), "=r"(r[1]), "=r"(r[2]), "=r"(r[3]) : "r"(addr));
}
__device__ __forceinline__ void mma16816(float (&c)[4], const uint32_t a0, const uint32_t a1,
                                         const uint32_t a2, const uint32_t a3,
                                         const uint32_t b0, const uint32_t b1) {
    asm volatile("mma.sync.aligned.m16n8k16.row.col.f32.f16.f16.f32 "
                 "{%0,%1,%2,%3}, {%4,%5,%6,%7}, {%8,%9}, {%0,%1,%2,%3};"
                 : "+f"(c[0]), "+f"(c[1]), "+f"(c[2]), "+f"(c[3])
                 : "r"(a0), "r"(a1), "r"(a2), "r"(a3), "r"(b0), "r"(b1));
}
__device__ __forceinline__ void split2(float v, __half& hi, __half& lo) {
    hi = __float2half(v);
    lo = __float2half(v - __half2float(hi));
}
// store one fp16 element into tiled+swizzled layout; nch = total 32-col chunks of buffer
__device__ __forceinline__ void store_elem(__half* buf, int nch, int row, int k, __half v) {
    int t = row >> 7, rr = row & 127, c = k >> 5, kk = k & 31;
    uint32_t off = SWZ32((uint32_t)(rr * 64 + kk * 2));
    *(__half*)((char*)buf + (((size_t)(t * nch + c)) << 13) + off) = v;
}

// ---------------- weight conversion: W[K,N] f32 -> tiled fp16 rows ----------------
__global__ void convert_w(const float* __restrict__ W, __half* __restrict__ out,
                          int K, int N, int rowOff) {
    __shared__ float t[32][33];
    int k0 = blockIdx.x * 32, n0 = blockIdx.y * 32;
    int tx = threadIdx.x & 31, ty = threadIdx.x >> 5;
    int nch = K >> 5;
    #pragma unroll
    for (int i = 0; i < 4; i++)
        t[ty + i * 8][tx] = W[(size_t)(k0 + ty + i * 8) * N + n0 + tx];
    __syncthreads();
    #pragma unroll
    for (int i = 0; i < 4; i++) {
        int n = rowOff + n0 + ty + i * 8, k = k0 + tx;
        store_elem(out, nch, n, k, __float2half(t[tx][ty + i * 8]));
    }
}
// fused QKV: blockIdx.z selects Wq/Wk/Wv, rowOff = z*D
__global__ void convert_qkv(const float* __restrict__ Wq, const float* __restrict__ Wk,
                            const float* __restrict__ Wv, __half* __restrict__ out) {
    __shared__ float t[32][33];
    const float* W = (blockIdx.z == 0) ? Wq : (blockIdx.z == 1) ? Wk : Wv;
    int k0 = blockIdx.x * 32, n0 = blockIdx.y * 32;
    int tx = threadIdx.x & 31, ty = threadIdx.x >> 5;
    #pragma unroll
    for (int i = 0; i < 4; i++)
        t[ty + i * 8][tx] = W[(size_t)(k0 + ty + i * 8) * D + n0 + tx];
    __syncthreads();
    #pragma unroll
    for (int i = 0; i < 4; i++) {
        int n = blockIdx.z * D + n0 + ty + i * 8, k = k0 + tx;
        store_elem(out, D >> 5, n, k, __float2half(t[tx][ty + i * 8]));
    }
}
__global__ void concat_bias(const float* __restrict__ a, const float* __restrict__ b,
                            const float* __restrict__ c, float* __restrict__ o) {
    int i = blockIdx.x * 256 + threadIdx.x;
    if (i < D) { o[i] = a[i]; o[D + i] = b[i]; o[2 * D + i] = c[i]; }
}

// ---------------- GEMM: C[2048,N] = A @ B^T, fp16 2-phase (A=[hi|lo], B=fp16) ----
// Tile 128x128, 8 warps (4M x 2N), warp tile 32x64. K-chunk 32.
// Stage=[A_hi 8K|A_lo 8K|B 8K]=24KB, NSTG=4 -> 96KB; <=128 regs -> 2 CTAs/SM.
__global__ void __launch_bounds__(256, 2) gemm_kernel(
    const __half* __restrict__ A, const __half* __restrict__ B,
    const float* __restrict__ bias, float* __restrict__ C, __half* __restrict__ S,
    int Kp, int N, int act)
{
    extern __shared__ __align__(128) char smem[];
    const int tid = threadIdx.x, wid = tid >> 5, lane = tid & 31;
    const int wm = wid & 3, wn = wid >> 2;
    const int m0 = blockIdx.x * 128, n0 = blockIdx.y * 128;
    const uint32_t sb = s2u(smem);
    const uint32_t MB = sb + NSTG * STG;
    const int nch0 = Kp / 32;

    if (tid == 0) {
        #pragma unroll
        for (int s = 0; s < NSTG; s++) mbar_init(MB + 8 * s, 1);
    }
    __syncthreads();

    auto issue = [&](int kk) {
        int s = kk & (NSTG - 1);
        uint32_t mb = MB + 8 * s, dst = sb + s * STG;
        mbar_expect(mb, 3 * 8192);
        bulk_ld(dst, (const char*)A + (((size_t)(blockIdx.x * 2 * nch0 + kk)) << 13), 8192, mb);
        bulk_ld(dst + 8192, (const char*)A + (((size_t)(blockIdx.x * 2 * nch0 + nch0 + kk)) << 13), 8192, mb);
        bulk_ld(dst + 16384, (const char*)B + (((size_t)(blockIdx.y * nch0 + kk)) << 13), 8192, mb);
    };
    if (tid == 0) { issue(0); issue(1); issue(2); }

    float acc[2][8][4];
    #pragma unroll
    for (int mi = 0; mi < 2; mi++)
        #pragma unroll
        for (int ni = 0; ni < 8; ni++)
            #pragma unroll
            for (int j = 0; j < 4; j++) acc[mi][ni][j] = 0.f;

    const int lq = lane & 7, lh = (lane >> 3) & 1, lk = lane >> 4;

    for (int kk = 0; kk < nch0; kk++) {
        mbar_wait(MB + 8 * (kk & (NSTG - 1)), (kk >> 2) & 1);
        uint32_t stg = sb + (kk & (NSTG - 1)) * STG;
        uint32_t bstg = stg + 16384;
        #pragma unroll
        for (int p = 0; p < 2; p++) {
            uint32_t astg = stg + p * 8192;
            #pragma unroll
            for (int ks = 0; ks < 2; ks++) {
                uint32_t af[2][4], bf[4][4];
                #pragma unroll
                for (int mt = 0; mt < 2; mt++) {
                    int r = wm * 32 + mt * 16 + lh * 8 + lq;
                    int sl = (ks * 2 + lk) ^ ((r >> 1) & 3);
                    ldm4(af[mt], astg + r * 64 + (sl << 4));
                }
                #pragma unroll
                for (int nt = 0; nt < 4; nt++) {
                    int r = wn * 64 + nt * 16 + lh * 8 + lq;
                    int sl = (ks * 2 + lk) ^ ((r >> 1) & 3);
                    ldm4(bf[nt], bstg + r * 64 + (sl << 4));
                }
                #pragma unroll
                for (int mi = 0; mi < 2; mi++)
                    #pragma unroll
                    for (int ni = 0; ni < 8; ni++) {
                        uint32_t b0 = bf[ni >> 1][ni & 1], b1 = bf[ni >> 1][(ni & 1) + 2];
                        mma16816(acc[mi][ni], af[mi][0], af[mi][1], af[mi][2], af[mi][3], b0, b1);
                    }
            }
        }
        __syncthreads();
        if (tid == 0 && kk + NSTG - 1 < nch0) issue(kk + NSTG - 1);
    }

    const int r0 = lane >> 2, cp = (lane & 3) * 2;
    const int nchS = N >> 4;   // chunks of (2N)-extent buffer = 2N/32 = N/16
    #pragma unroll
    for (int mi = 0; mi < 2; mi++) {
        #pragma unroll
        for (int ni = 0; ni < 8; ni++) {
            int col = n0 + wn * 64 + ni * 8 + cp;
            float bb0 = bias[col], bb1 = bias[col + 1];
            #pragma unroll
            for (int half = 0; half < 2; half++) {
                int row = m0 + wm * 32 + mi * 16 + r0 + half * 8;
                float v0 = acc[mi][ni][half * 2 + 0] + bb0;
                float v1 = acc[mi][ni][half * 2 + 1] + bb1;
                if (act) {
                    v0 = 0.5f * v0 * (1.0f + erff(v0 * 0.70710678118654752f));
                    v1 = 0.5f * v1 * (1.0f + erff(v1 * 0.70710678118654752f));
                }
                if (C) {
                    float2 o; o.x = v0; o.y = v1;
                    *(float2*)(C + (size_t)row * N + col) = o;
                }
                if (S) {
                    __half h0, l0, h1, l1;
                    split2(v0, h0, l0); split2(v1, h1, l1);
                    int t = row >> 7, rr = row & 127;
                    uint32_t off = SWZ32((uint32_t)(rr * 64 + (col & 31) * 2));
                    __half2 hp; hp.x = h0; hp.y = h1;
                    *(__half2*)((char*)S + (((size_t)(t * nchS + (col >> 5))) << 13) + off) = hp;
                    __half2 lp; lp.x = l0; lp.y = l1;
                    *(__half2*)((char*)S + (((size_t)(t * nchS + ((N + col) >> 5))) << 13) + off) = lp;
                }
            }
        }
    }
}

// ---------------- LayerNorm ----------------
__device__ __forceinline__ float brsum(float v, float* sbuf) {
    int tid = threadIdx.x;
    #pragma unroll
    for (int o = 16; o; o >>= 1) v += __shfl_down_sync(0xffffffffu, v, o);
    if ((tid & 31) == 0) sbuf[tid >> 5] = v;
    __syncthreads();
    if (tid < 8) {
        v = sbuf[tid];
        #pragma unroll
        for (int o = 4; o; o >>= 1) v += __shfl_down_sync(0xffu, v, o);
        if (tid == 0) sbuf[0] = v;
    }
    __syncthreads();
    float r = sbuf[0];
    __syncthreads();
    return r;
}
__global__ void embed_ln_kernel(const int* __restrict__ x, const int* __restrict__ len,
                                const float* __restrict__ tok, const float* __restrict__ pos,
                                const float* __restrict__ g, const float* __restrict__ b,
                                float* __restrict__ out, __half* __restrict__ sp) {
    int row = blockIdx.x, bi = row / SLEN, s = row % SLEN, token = x[row], tid = threadIdx.x;
    __shared__ float buf[D]; __shared__ float red[8];
    float ls = 0.f;
    #pragma unroll
    for (int i = 0; i < 4; i++) {
        int c = tid + i * 256;
        float v = tok[(size_t)token * D + c] + pos[(size_t)s * D + c];
        buf[c] = v; ls += v;
    }
    float mean = brsum(ls, red) * (1.0f / D), ss = 0.f;
    #pragma unroll
    for (int i = 0; i < 4; i++) { float d = buf[tid + i * 256] - mean; ss += d * d; }
    float rstd = rsqrtf(brsum(ss, red) * (1.0f / D) + EPS);
    float mask = (s < len[bi]) ? 1.0f : 0.0f;
    #pragma unroll
    for (int i = 0; i < 4; i++) {
        int c = tid + i * 256;
        float v = (g[c] * (buf[c] - mean) * rstd + b[c]) * mask;
        out[(size_t)row * D + c] = v;
        __half hi, lo; split2(v, hi, lo);
        store_elem(sp, 64, row, c, hi);
        store_elem(sp, 64, row, D + c, lo);
    }
}
__global__ void add_ln_kernel(const float* __restrict__ a, const float* __restrict__ dl,
                              const float* __restrict__ g, const float* __restrict__ b,
                              const int* __restrict__ len, float* __restrict__ out,
                              __half* __restrict__ sp) {
    int row = blockIdx.x, bi = row / SLEN, s = row % SLEN, tid = threadIdx.x;
    __shared__ float buf[D]; __shared__ float red[8];
    float ls = 0.f;
    #pragma unroll
    for (int i = 0; i < 4; i++) {
        int c = tid + i * 256;
        float v = a[(size_t)row * D + c] + dl[(size_t)row * D + c];
        buf[c] = v; ls += v;
    }
    float mean = brsum(ls, red) * (1.0f / D), ss = 0.f;
    #pragma unroll
    for (int i = 0; i < 4; i++) { float d = buf[tid + i * 256] - mean; ss += d * d; }
    float rstd = rsqrtf(brsum(ss, red) * (1.0f / D) + EPS);
    float mask = len ? ((s < len[bi]) ? 1.0f : 0.0f) : 1.0f;
    #pragma unroll
    for (int i = 0; i < 4; i++) {
        int c = tid + i * 256;
        float v = (g[c] * (buf[c] - mean) * rstd + b[c]) * mask;
        out[(size_t)row * D + c] = v;
        __half hi, lo; split2(v, hi, lo);
        store_elem(sp, 64, row, c, hi);
        store_elem(sp, 64, row, D + c, lo);
    }
}

// ---------------- attention: 8 q/block, smem-staged K/V, warp softmax ----
#define QT 8
#define KCH 128
#define ATTN_SMEM ((QT*DH + QT*SLEN + KCH*65 + QT) * 4)
__global__ void attn_kernel(const float* __restrict__ qkv, __half* __restrict__ a3) {
    extern __shared__ float sm[];
    float* sq = sm;
    float* sc = sq + QT * DH;
    float* sk = sc + QT * SLEN;
    float* sinv = sk + KCH * 65;
    const int q0 = blockIdx.x * QT, hd = blockIdx.y, bb = blockIdx.z, tid = threadIdx.x;
    const int wid = tid >> 5, lane = tid & 31;
    const int nkb = q0 + QT;
    const size_t rb = (size_t)(bb * SLEN) * K3D + (size_t)hd * DH;

    for (int i = tid; i < QT * DH; i += 128)
        sq[i] = qkv[rb + (size_t)(q0 + i / DH) * K3D + (i % DH)] * 0.125f;
    __syncthreads();

    const float* kb = qkv + rb + D;
    for (int c0 = 0; c0 < nkb; c0 += KCH) {
        int rows = nkb - c0; if (rows > KCH) rows = KCH;
        for (int idx = tid; idx < rows * 16; idx += 128) {
            int r = idx >> 4, c4 = (idx & 15) * 4;
            float4 v = *(const float4*)(kb + (size_t)(c0 + r) * K3D + c4);
            sk[r * 65 + c4 + 0] = v.x; sk[r * 65 + c4 + 1] = v.y;
            sk[r * 65 + c4 + 2] = v.z; sk[r * 65 + c4 + 3] = v.w;
        }
        __syncthreads();
        for (int key = tid; key < rows; key += 128) {
            float a[QT];
            #pragma unroll
            for (int qi = 0; qi < QT; qi++) a[qi] = 0.f;
            #pragma unroll 8
            for (int d = 0; d < DH; d++) {
                float kd = sk[key * 65 + d];
                #pragma unroll
                for (int qi = 0; qi < QT; qi++) a[qi] = fmaf(sq[qi * DH + d], kd, a[qi]);
            }
            #pragma unroll
            for (int qi = 0; qi < QT; qi++) sc[qi * SLEN + c0 + key] = a[qi];
        }
        __syncthreads();
    }

    #pragma unroll
    for (int t = 0; t < 2; t++) {
        int qi = wid * 2 + t, bound = q0 + qi;
        float mx = -1e30f;
        for (int key = lane; key <= bound; key += 32) mx = fmaxf(mx, sc[qi * SLEN + key]);
        #pragma unroll
        for (int o = 16; o; o >>= 1) mx = fmaxf(mx, __shfl_xor_sync(0xffffffffu, mx, o));
        float s = 0.f;
        for (int key = lane; key < nkb; key += 32) {
            float e = (key <= bound) ? expf(sc[qi * SLEN + key] - mx) : 0.f;
            sc[qi * SLEN + key] = e; s += e;
        }
        #pragma unroll
        for (int o = 16; o; o >>= 1) s += __shfl_xor_sync(0xffffffffu, s, o);
        if (lane == 0) sinv[qi] = 1.0f / s;
    }
    __syncthreads();

    const int d = tid & 63, half = tid >> 6;
    const float* vb = qkv + rb + 2 * D;
    float a[QT];
    #pragma unroll
    for (int qi = 0; qi < QT; qi++) a[qi] = 0.f;
    for (int c0 = 0; c0 < nkb; c0 += KCH) {
        int rows = nkb - c0; if (rows > KCH) rows = KCH;
        for (int idx = tid; idx < rows * 16; idx += 128) {
            int r = idx >> 4, c4 = (idx & 15) * 4;
            float4 v = *(const float4*)(vb + (size_t)(c0 + r) * K3D + c4);
            sk[r * 65 + c4 + 0] = v.x; sk[r * 65 + c4 + 1] = v.y;
            sk[r * 65 + c4 + 2] = v.z; sk[r * 65 + c4 + 3] = v.w;
        }
        __syncthreads();
        for (int key = half; key < rows; key += 2) {
            float vv = sk[key * 65 + d];
            #pragma unroll
            for (int qi = 0; qi < QT; qi++)
                a[qi] = fmaf(sc[qi * SLEN + c0 + key], vv, a[qi]);
        }
        __syncthreads();
    }
    for (int qi = 0; qi < QT; qi++) {
        sk[tid] = a[qi]; __syncthreads();
        if (tid < 64) {
            float v = (sk[tid] + sk[tid + 64]) * sinv[qi];
            int row = bb * SLEN + q0 + qi;
            __half hi, lo; split2(v, hi, lo);
            store_elem(a3, 64, row, hd * DH + d, hi);
            store_elem(a3, 64, row, D + hd * DH + d, lo);
        }
        __syncthreads();
    }
}

// ---------------- launcher ----------------
extern "C" void kernel_launch(void* const* d_in, const int* in_sizes, int n_in,
                              void* d_out, int out_size) {
    const int*   x   = (const int*)  d_in[0];
    const int*   len = (const int*)  d_in[1];
    const float* tok = (const float*)d_in[2];
    const float* pos = (const float*)d_in[3];
    const float* leg = (const float*)d_in[4];
    const float* leb = (const float*)d_in[5];
    const float* Wq = (const float*)d_in[6];  const float* bq = (const float*)d_in[7];
    const float* Wk = (const float*)d_in[8];  const float* bk = (const float*)d_in[9];
    const float* Wv = (const float*)d_in[10]; const float* bv = (const float*)d_in[11];
    const float* Wo = (const float*)d_in[12]; const float* bo = (const float*)d_in[13];
    const float* l1g = (const float*)d_in[14]; const float* l1b = (const float*)d_in[15];
    const float* W1 = (const float*)d_in[16]; const float* b1 = (const float*)d_in[17];
    const float* W2 = (const float*)d_in[18]; const float* b2 = (const float*)d_in[19];
    const float* l2g = (const float*)d_in[20]; const float* l2b = (const float*)d_in[21];
    const float* pW = (const float*)d_in[22]; const float* pb = (const float*)d_in[23];
    float* out = (float*)d_out;

    float *h, *qkv, *tmp, *bqkv;
    __half *a3, *s2, *wqkv, *wo, *w1, *w2, *wp;
    cudaGetSymbolAddress((void**)&h, g_h);     cudaGetSymbolAddress((void**)&qkv, g_qkv);
    cudaGetSymbolAddress((void**)&tmp, g_tmp); cudaGetSymbolAddress((void**)&bqkv, g_bqkv);
    cudaGetSymbolAddress((void**)&a3, g_a3);   cudaGetSymbolAddress((void**)&s2, g_s2);
    cudaGetSymbolAddress((void**)&wqkv, g_wqkv); cudaGetSymbolAddress((void**)&wo, g_wo);
    cudaGetSymbolAddress((void**)&w1, g_w1);   cudaGetSymbolAddress((void**)&w2, g_w2);
    cudaGetSymbolAddress((void**)&wp, g_wp);

    const int smg = NSTG * STG + 64;   // 98368
    cudaFuncSetAttribute(gemm_kernel, cudaFuncAttributeMaxDynamicSharedMemorySize, smg);
    cudaFuncSetAttribute(attn_kernel, cudaFuncAttributeMaxDynamicSharedMemorySize, ATTN_SMEM);

    // launch order chosen so index 3 (the ncu-captured launch) is the QKV GEMM
    embed_ln_kernel<<<TOK, 256>>>(x, len, tok, pos, leg, leb, h, a3);          // 0
    convert_qkv<<<dim3(D/32, D/32, 3), 256>>>(Wq, Wk, Wv, wqkv);               // 1
    concat_bias<<<4, 256>>>(bq, bk, bv, bqkv);                                 // 2
    gemm_kernel<<<dim3(TOK/128, K3D/128), 256, smg>>>(                         // 3  <-- profiled
        a3, wqkv, bqkv, qkv, (__half*)0, D, K3D, 0);

    convert_w<<<dim3(D/32, D/32), 256>>>(Wo, wo, D, D, 0);
    convert_w<<<dim3(D/32, FF/32), 256>>>(W1, w1, D, FF, 0);
    convert_w<<<dim3(FF/32, D/32), 256>>>(W2, w2, FF, D, 0);
    {
        size_t w = (size_t)D * D;
        convert_qkv<<<dim3(D/32, D/32, 3), 256>>>(Wq + w, Wk + w, Wv + w, wqkv + (size_t)K3D * D);
        convert_w<<<dim3(D/32, D/32), 256>>>(Wo + w, wo + (size_t)D*D, D, D, 0);
        convert_w<<<dim3(D/32, FF/32), 256>>>(W1 + (size_t)D*FF, w1 + (size_t)FF*D, D, FF, 0);
        convert_w<<<dim3(FF/32, D/32), 256>>>(W2 + (size_t)FF*D, w2 + (size_t)D*FF, FF, D, 0);
        concat_bias<<<4, 256>>>(bq + D, bk + D, bv + D, bqkv + K3D);
    }
    convert_w<<<dim3(D/32, V/32), 256>>>(pW, wp, D, V, 0);

    for (int i = 0; i < LYRS; i++) {
        if (i > 0)
            gemm_kernel<<<dim3(TOK/128, K3D/128), 256, smg>>>(
                a3, wqkv + (size_t)i*K3D*D, bqkv + (size_t)i*K3D, qkv, (__half*)0, D, K3D, 0);

        attn_kernel<<<dim3(SLEN/QT, H, BS), 128, ATTN_SMEM>>>(qkv, a3);

        gemm_kernel<<<dim3(TOK/128, D/128), 256, smg>>>(
            a3, wo + (size_t)i*D*D, bo + (size_t)i*D, tmp, (__half*)0, D, D, 0);
        add_ln_kernel<<<TOK, 256>>>(h, tmp, l1g + (size_t)i*D, l1b + (size_t)i*D, (const int*)0, h, a3);

        gemm_kernel<<<dim3(TOK/128, FF/128), 256, smg>>>(
            a3, w1 + (size_t)i*FF*D, b1 + (size_t)i*FF, (float*)0, s2, D, FF, 1);

        gemm_kernel<<<dim3(TOK/128, D/128), 256, smg>>>(
            s2, w2 + (size_t)i*D*FF, b2 + (size_t)i*D, tmp, (__half*)0, FF, D, 0);
        add_ln_kernel<<<TOK, 256>>>(h, tmp, l2g + (size_t)i*D, l2b + (size_t)i*D, len, h, a3);
    }

    gemm_kernel<<<dim3(TOK/128, V/128), 256, smg>>>(
        a3, wp, pb, out, (__half*)0, D, V, 0);
}

// round 14
// speedup vs baseline: 1.0977x; 1.0098x over previous
#include <cuda_runtime.h>
#include <cuda_fp16.h>
#include <math.h>
#include <stdint.h>

#define LYRS 2
#define H 16
#define D 1024
#define DH 64
#define FF 4096
#define V 32000
#define SLEN 1024
#define BS 2
#define TOK (BS*SLEN)
#define EPS 1e-12f
#define K3D (3*D)
#define NSTG 4
#define STG (3*8192)

// ---------------- scratch ----------------
__device__ float g_h  [TOK*D];
__device__ float g_qkv[TOK*K3D];
__device__ float g_tmp[TOK*D];
__device__ float g_bqkv[LYRS*K3D];
// fp16 operand buffers, tiled layout [rowTile128][kChunk32][128x32 sw64-swizzled 8KB]
__device__ __align__(256) __half g_a3 [TOK*2*D];
__device__ __align__(256) __half g_s2 [TOK*2*FF];
__device__ __align__(256) __half g_wqkv[LYRS*(size_t)K3D*D];
__device__ __align__(256) __half g_wo  [LYRS*(size_t)D*D];
__device__ __align__(256) __half g_w1  [LYRS*(size_t)FF*D];
__device__ __align__(256) __half g_w2  [LYRS*(size_t)D*FF];
__device__ __align__(256) __half g_wp  [(size_t)V*D];

// ---------------- helpers ----------------
__device__ __forceinline__ uint32_t s2u(const void* p) {
    uint32_t a;
    asm("{ .reg .u64 t; cvta.to.shared.u64 t, %1; cvt.u32.u64 %0, t; }" : "=r"(a) : "l"(p));
    return a;
}
#define SWZ32(o) ((o) ^ (((o) >> 3) & 0x30))
__device__ __forceinline__ void mbar_init(uint32_t a, uint32_t c) {
    asm volatile("mbarrier.init.shared.b64 [%0], %1;" :: "r"(a), "r"(c) : "memory");
}
__device__ __forceinline__ void mbar_expect(uint32_t a, uint32_t tx) {
    asm volatile("mbarrier.arrive.expect_tx.shared.b64 _, [%0], %1;" :: "r"(a), "r"(tx) : "memory");
}
__device__ __forceinline__ void mbar_arrive(uint32_t a) {
    asm volatile("mbarrier.arrive.shared.b64 _, [%0];" :: "r"(a) : "memory");
}
__device__ __forceinline__ void mbar_wait(uint32_t a, uint32_t ph) {
    asm volatile(
        "{\n\t.reg .pred P;\n\tL_%=:\n\t"
        "mbarrier.try_wait.parity.acquire.cta.shared::cta.b64 P, [%0], %1, 0x989680;\n\t"
        "@P bra D_%=;\n\tbra L_%=;\n\tD_%=:\n\t}" :: "r"(a), "r"(ph) : "memory");
}
__device__ __forceinline__ void bulk_ld(uint32_t dst, const void* src, uint32_t bytes, uint32_t mbar) {
    asm volatile("cp.async.bulk.shared::cta.global.mbarrier::complete_tx::bytes [%0], [%1], %2, [%3];"
                 :: "r"(dst), "l"(src), "r"(bytes), "r"(mbar) : "memory");
}
__device__ __forceinline__ void ldm4(uint32_t (&r)[4], uint32_t addr) {
    asm volatile("ldmatrix.sync.aligned.m8n8.x4.shared.b16 {%0,%1,%2,%3}, [%4];"
                 : "=r"(r[0]), "=r"(r[1]), "=r"(r[2]), "=r"(r[3]) : "r"(addr));
}
__device__ __forceinline__ void mma16816(float (&c)[4], const uint32_t a0, const uint32_t a1,
                                         const uint32_t a2, const uint32_t a3,
                                         const uint32_t b0, const uint32_t b1) {
    asm volatile("mma.sync.aligned.m16n8k16.row.col.f32.f16.f16.f32 "
                 "{%0,%1,%2,%3}, {%4,%5,%6,%7}, {%8,%9}, {%0,%1,%2,%3};"
                 : "+f"(c[0]), "+f"(c[1]), "+f"(c[2]), "+f"(c[3])
                 : "r"(a0), "r"(a1), "r"(a2), "r"(a3), "r"(b0), "r"(b1));
}
__device__ __forceinline__ void split2(float v, __half& hi, __half& lo) {
    hi = __float2half(v);
    lo = __float2half(v - __half2float(hi));
}
__device__ __forceinline__ void store_elem(__half* buf, int nch, int row, int k, __half v) {
    int t = row >> 7, rr = row & 127, c = k >> 5, kk = k & 31;
    uint32_t off = SWZ32((uint32_t)(rr * 64 + kk * 2));
    *(__half*)((char*)buf + (((size_t)(t * nch + c)) << 13) + off) = v;
}

// ---------------- weight conversion ----------------
__global__ void convert_w(const float* __restrict__ W, __half* __restrict__ out,
                          int K, int N, int rowOff) {
    __shared__ float t[32][33];
    int k0 = blockIdx.x * 32, n0 = blockIdx.y * 32;
    int tx = threadIdx.x & 31, ty = threadIdx.x >> 5;
    int nch = K >> 5;
    #pragma unroll
    for (int i = 0; i < 4; i++)
        t[ty + i * 8][tx] = W[(size_t)(k0 + ty + i * 8) * N + n0 + tx];
    __syncthreads();
    #pragma unroll
    for (int i = 0; i < 4; i++) {
        int n = rowOff + n0 + ty + i * 8, k = k0 + tx;
        store_elem(out, nch, n, k, __float2half(t[tx][ty + i * 8]));
    }
}
__global__ void convert_qkv(const float* __restrict__ Wq, const float* __restrict__ Wk,
                            const float* __restrict__ Wv, __half* __restrict__ out) {
    __shared__ float t[32][33];
    const float* W = (blockIdx.z == 0) ? Wq : (blockIdx.z == 1) ? Wk : Wv;
    int k0 = blockIdx.x * 32, n0 = blockIdx.y * 32;
    int tx = threadIdx.x & 31, ty = threadIdx.x >> 5;
    #pragma unroll
    for (int i = 0; i < 4; i++)
        t[ty + i * 8][tx] = W[(size_t)(k0 + ty + i * 8) * D + n0 + tx];
    __syncthreads();
    #pragma unroll
    for (int i = 0; i < 4; i++) {
        int n = blockIdx.z * D + n0 + ty + i * 8, k = k0 + tx;
        store_elem(out, D >> 5, n, k, __float2half(t[tx][ty + i * 8]));
    }
}
__global__ void concat_bias(const float* __restrict__ a, const float* __restrict__ b,
                            const float* __restrict__ c, float* __restrict__ o) {
    int i = blockIdx.x * 256 + threadIdx.x;
    if (i < D) { o[i] = a[i]; o[D + i] = b[i]; o[2 * D + i] = c[i]; }
}

// ---------------- GEMM: producer/consumer mbarriers, no per-chunk syncthreads ----
// Tile 128x128, 8 warps (4M x 2N), warp tile 32x64, K-chunk 32, NSTG=4, 2 CTAs/SM.
__global__ void __launch_bounds__(256, 2) gemm_kernel(
    const __half* __restrict__ A, const __half* __restrict__ B,
    const float* __restrict__ bias, float* __restrict__ C, __half* __restrict__ S,
    int Kp, int N, int act)
{
    extern __shared__ __align__(128) char smem[];
    const int tid = threadIdx.x, wid = tid >> 5, lane = tid & 31;
    const int wm = wid & 3, wn = wid >> 2;
    const int m0 = blockIdx.x * 128, n0 = blockIdx.y * 128;
    const uint32_t sb = s2u(smem);
    const uint32_t FB = sb + NSTG * STG;        // full barriers (tx)
    const uint32_t EB = FB + NSTG * 8;          // empty barriers (8 warp arrivals)
    const int nch0 = Kp / 32;

    if (tid == 0) {
        #pragma unroll
        for (int s = 0; s < NSTG; s++) { mbar_init(FB + 8 * s, 1); mbar_init(EB + 8 * s, 8); }
    }
    __syncthreads();

    auto issue = [&](int kk) {
        int s = kk & (NSTG - 1);
        uint32_t mb = FB + 8 * s, dst = sb + s * STG;
        mbar_expect(mb, 3 * 8192);
        bulk_ld(dst, (const char*)A + (((size_t)(blockIdx.x * 2 * nch0 + kk)) << 13), 8192, mb);
        bulk_ld(dst + 8192, (const char*)A + (((size_t)(blockIdx.x * 2 * nch0 + nch0 + kk)) << 13), 8192, mb);
        bulk_ld(dst + 16384, (const char*)B + (((size_t)(blockIdx.y * nch0 + kk)) << 13), 8192, mb);
    };
    if (tid == 0) { issue(0); issue(1); issue(2); }

    float acc[2][8][4];
    #pragma unroll
    for (int mi = 0; mi < 2; mi++)
        #pragma unroll
        for (int ni = 0; ni < 8; ni++)
            #pragma unroll
            for (int j = 0; j < 4; j++) acc[mi][ni][j] = 0.f;

    const int lq = lane & 7, lh = (lane >> 3) & 1, lk = lane >> 4;

    for (int kk = 0; kk < nch0; kk++) {
        int s = kk & (NSTG - 1);
        mbar_wait(FB + 8 * s, (kk >> 2) & 1);
        uint32_t stg = sb + s * STG;
        uint32_t bstg = stg + 16384;
        #pragma unroll
        for (int p = 0; p < 2; p++) {
            uint32_t astg = stg + p * 8192;
            #pragma unroll
            for (int ks = 0; ks < 2; ks++) {
                uint32_t af[2][4], bf[4][4];
                #pragma unroll
                for (int mt = 0; mt < 2; mt++) {
                    int r = wm * 32 + mt * 16 + lh * 8 + lq;
                    int sl = (ks * 2 + lk) ^ ((r >> 1) & 3);
                    ldm4(af[mt], astg + r * 64 + (sl << 4));
                }
                #pragma unroll
                for (int nt = 0; nt < 4; nt++) {
                    int r = wn * 64 + nt * 16 + lh * 8 + lq;
                    int sl = (ks * 2 + lk) ^ ((r >> 1) & 3);
                    ldm4(bf[nt], bstg + r * 64 + (sl << 4));
                }
                #pragma unroll
                for (int mi = 0; mi < 2; mi++)
                    #pragma unroll
                    for (int ni = 0; ni < 8; ni++) {
                        uint32_t b0 = bf[ni >> 1][ni & 1], b1 = bf[ni >> 1][(ni & 1) + 2];
                        mma16816(acc[mi][ni], af[mi][0], af[mi][1], af[mi][2], af[mi][3], b0, b1);
                    }
            }
        }
        if (lane == 0) mbar_arrive(EB + 8 * s);
        // producer: issue chunk kk+NSTG-1 after its slot's previous occupant is drained
        if (tid == 0) {
            int cc = kk + NSTG - 1;
            if (cc < nch0) {
                if (cc >= NSTG) mbar_wait(EB + 8 * (cc & (NSTG - 1)), ((cc >> 2) + 1) & 1);
                issue(cc);
            }
        }
    }

    const int r0 = lane >> 2, cp = (lane & 3) * 2;
    const int nchS = N >> 4;
    #pragma unroll
    for (int mi = 0; mi < 2; mi++) {
        #pragma unroll
        for (int ni = 0; ni < 8; ni++) {
            int col = n0 + wn * 64 + ni * 8 + cp;
            float bb0 = bias[col], bb1 = bias[col + 1];
            #pragma unroll
            for (int half = 0; half < 2; half++) {
                int row = m0 + wm * 32 + mi * 16 + r0 + half * 8;
                float v0 = acc[mi][ni][half * 2 + 0] + bb0;
                float v1 = acc[mi][ni][half * 2 + 1] + bb1;
                if (act) {
                    v0 = 0.5f * v0 * (1.0f + erff(v0 * 0.70710678118654752f));
                    v1 = 0.5f * v1 * (1.0f + erff(v1 * 0.70710678118654752f));
                }
                if (C) {
                    float2 o; o.x = v0; o.y = v1;
                    *(float2*)(C + (size_t)row * N + col) = o;
                }
                if (S) {
                    __half h0, l0, h1, l1;
                    split2(v0, h0, l0); split2(v1, h1, l1);
                    int t = row >> 7, rr = row & 127;
                    uint32_t off = SWZ32((uint32_t)(rr * 64 + (col & 31) * 2));
                    __half2 hp; hp.x = h0; hp.y = h1;
                    *(__half2*)((char*)S + (((size_t)(t * nchS + (col >> 5))) << 13) + off) = hp;
                    __half2 lp; lp.x = l0; lp.y = l1;
                    *(__half2*)((char*)S + (((size_t)(t * nchS + ((N + col) >> 5))) << 13) + off) = lp;
                }
            }
        }
    }
}

// ---------------- LayerNorm ----------------
__device__ __forceinline__ float brsum(float v, float* sbuf) {
    int tid = threadIdx.x;
    #pragma unroll
    for (int o = 16; o; o >>= 1) v += __shfl_down_sync(0xffffffffu, v, o);
    if ((tid & 31) == 0) sbuf[tid >> 5] = v;
    __syncthreads();
    if (tid < 8) {
        v = sbuf[tid];
        #pragma unroll
        for (int o = 4; o; o >>= 1) v += __shfl_down_sync(0xffu, v, o);
        if (tid == 0) sbuf[0] = v;
    }
    __syncthreads();
    float r = sbuf[0];
    __syncthreads();
    return r;
}
__global__ void embed_ln_kernel(const int* __restrict__ x, const int* __restrict__ len,
                                const float* __restrict__ tok, const float* __restrict__ pos,
                                const float* __restrict__ g, const float* __restrict__ b,
                                float* __restrict__ out, __half* __restrict__ sp) {
    int row = blockIdx.x, bi = row / SLEN, s = row % SLEN, token = x[row], tid = threadIdx.x;
    __shared__ float buf[D]; __shared__ float red[8];
    float ls = 0.f;
    #pragma unroll
    for (int i = 0; i < 4; i++) {
        int c = tid + i * 256;
        float v = tok[(size_t)token * D + c] + pos[(size_t)s * D + c];
        buf[c] = v; ls += v;
    }
    float mean = brsum(ls, red) * (1.0f / D), ss = 0.f;
    #pragma unroll
    for (int i = 0; i < 4; i++) { float d = buf[tid + i * 256] - mean; ss += d * d; }
    float rstd = rsqrtf(brsum(ss, red) * (1.0f / D) + EPS);
    float mask = (s < len[bi]) ? 1.0f : 0.0f;
    #pragma unroll
    for (int i = 0; i < 4; i++) {
        int c = tid + i * 256;
        float v = (g[c] * (buf[c] - mean) * rstd + b[c]) * mask;
        out[(size_t)row * D + c] = v;
        __half hi, lo; split2(v, hi, lo);
        store_elem(sp, 64, row, c, hi);
        store_elem(sp, 64, row, D + c, lo);
    }
}
__global__ void add_ln_kernel(const float* __restrict__ a, const float* __restrict__ dl,
                              const float* __restrict__ g, const float* __restrict__ b,
                              const int* __restrict__ len, float* __restrict__ out,
                              __half* __restrict__ sp) {
    int row = blockIdx.x, bi = row / SLEN, s = row % SLEN, tid = threadIdx.x;
    __shared__ float buf[D]; __shared__ float red[8];
    float ls = 0.f;
    #pragma unroll
    for (int i = 0; i < 4; i++) {
        int c = tid + i * 256;
        float v = a[(size_t)row * D + c] + dl[(size_t)row * D + c];
        buf[c] = v; ls += v;
    }
    float mean = brsum(ls, red) * (1.0f / D), ss = 0.f;
    #pragma unroll
    for (int i = 0; i < 4; i++) { float d = buf[tid + i * 256] - mean; ss += d * d; }
    float rstd = rsqrtf(brsum(ss, red) * (1.0f / D) + EPS);
    float mask = len ? ((s < len[bi]) ? 1.0f : 0.0f) : 1.0f;
    #pragma unroll
    for (int i = 0; i < 4; i++) {
        int c = tid + i * 256;
        float v = (g[c] * (buf[c] - mean) * rstd + b[c]) * mask;
        out[(size_t)row * D + c] = v;
        __half hi, lo; split2(v, hi, lo);
        store_elem(sp, 64, row, c, hi);
        store_elem(sp, 64, row, D + c, lo);
    }
}

// ---------------- attention: 8 q/block, smem-staged K/V, warp softmax ----
#define QT 8
#define KCH 128
#define ATTN_SMEM ((QT*DH + QT*SLEN + KCH*65 + QT) * 4)
__global__ void attn_kernel(const float* __restrict__ qkv, __half* __restrict__ a3) {
    extern __shared__ float sm[];
    float* sq = sm;
    float* sc = sq + QT * DH;
    float* sk = sc + QT * SLEN;
    float* sinv = sk + KCH * 65;
    const int q0 = blockIdx.x * QT, hd = blockIdx.y, bb = blockIdx.z, tid = threadIdx.x;
    const int wid = tid >> 5, lane = tid & 31;
    const int nkb = q0 + QT;
    const size_t rb = (size_t)(bb * SLEN) * K3D + (size_t)hd * DH;

    for (int i = tid; i < QT * DH; i += 128)
        sq[i] = qkv[rb + (size_t)(q0 + i / DH) * K3D + (i % DH)] * 0.125f;
    __syncthreads();

    const float* kb = qkv + rb + D;
    for (int c0 = 0; c0 < nkb; c0 += KCH) {
        int rows = nkb - c0; if (rows > KCH) rows = KCH;
        for (int idx = tid; idx < rows * 16; idx += 128) {
            int r = idx >> 4, c4 = (idx & 15) * 4;
            float4 v = *(const float4*)(kb + (size_t)(c0 + r) * K3D + c4);
            sk[r * 65 + c4 + 0] = v.x; sk[r * 65 + c4 + 1] = v.y;
            sk[r * 65 + c4 + 2] = v.z; sk[r * 65 + c4 + 3] = v.w;
        }
        __syncthreads();
        for (int key = tid; key < rows; key += 128) {
            float a[QT];
            #pragma unroll
            for (int qi = 0; qi < QT; qi++) a[qi] = 0.f;
            #pragma unroll 8
            for (int d = 0; d < DH; d++) {
                float kd = sk[key * 65 + d];
                #pragma unroll
                for (int qi = 0; qi < QT; qi++) a[qi] = fmaf(sq[qi * DH + d], kd, a[qi]);
            }
            #pragma unroll
            for (int qi = 0; qi < QT; qi++) sc[qi * SLEN + c0 + key] = a[qi];
        }
        __syncthreads();
    }

    #pragma unroll
    for (int t = 0; t < 2; t++) {
        int qi = wid * 2 + t, bound = q0 + qi;
        float mx = -1e30f;
        for (int key = lane; key <= bound; key += 32) mx = fmaxf(mx, sc[qi * SLEN + key]);
        #pragma unroll
        for (int o = 16; o; o >>= 1) mx = fmaxf(mx, __shfl_xor_sync(0xffffffffu, mx, o));
        float s = 0.f;
        for (int key = lane; key < nkb; key += 32) {
            float e = (key <= bound) ? expf(sc[qi * SLEN + key] - mx) : 0.f;
            sc[qi * SLEN + key] = e; s += e;
        }
        #pragma unroll
        for (int o = 16; o; o >>= 1) s += __shfl_xor_sync(0xffffffffu, s, o);
        if (lane == 0) sinv[qi] = 1.0f / s;
    }
    __syncthreads();

    const int d = tid & 63, half = tid >> 6;
    const float* vb = qkv + rb + 2 * D;
    float a[QT];
    #pragma unroll
    for (int qi = 0; qi < QT; qi++) a[qi] = 0.f;
    for (int c0 = 0; c0 < nkb; c0 += KCH) {
        int rows = nkb - c0; if (rows > KCH) rows = KCH;
        for (int idx = tid; idx < rows * 16; idx += 128) {
            int r = idx >> 4, c4 = (idx & 15) * 4;
            float4 v = *(const float4*)(vb + (size_t)(c0 + r) * K3D + c4);
            sk[r * 65 + c4 + 0] = v.x; sk[r * 65 + c4 + 1] = v.y;
            sk[r * 65 + c4 + 2] = v.z; sk[r * 65 + c4 + 3] = v.w;
        }
        __syncthreads();
        for (int key = half; key < rows; key += 2) {
            float vv = sk[key * 65 + d];
            #pragma unroll
            for (int qi = 0; qi < QT; qi++)
                a[qi] = fmaf(sc[qi * SLEN + c0 + key], vv, a[qi]);
        }
        __syncthreads();
    }
    for (int qi = 0; qi < QT; qi++) {
        sk[tid] = a[qi]; __syncthreads();
        if (tid < 64) {
            float v = (sk[tid] + sk[tid + 64]) * sinv[qi];
            int row = bb * SLEN + q0 + qi;
            __half hi, lo; split2(v, hi, lo);
            store_elem(a3, 64, row, hd * DH + d, hi);
            store_elem(a3, 64, row, D + hd * DH + d, lo);
        }
        __syncthreads();
    }
}

// ---------------- launcher ----------------
extern "C" void kernel_launch(void* const* d_in, const int* in_sizes, int n_in,
                              void* d_out, int out_size) {
    const int*   x   = (const int*)  d_in[0];
    const int*   len = (const int*)  d_in[1];
    const float* tok = (const float*)d_in[2];
    const float* pos = (const float*)d_in[3];
    const float* leg = (const float*)d_in[4];
    const float* leb = (const float*)d_in[5];
    const float* Wq = (const float*)d_in[6];  const float* bq = (const float*)d_in[7];
    const float* Wk = (const float*)d_in[8];  const float* bk = (const float*)d_in[9];
    const float* Wv = (const float*)d_in[10]; const float* bv = (const float*)d_in[11];
    const float* Wo = (const float*)d_in[12]; const float* bo = (const float*)d_in[13];
    const float* l1g = (const float*)d_in[14]; const float* l1b = (const float*)d_in[15];
    const float* W1 = (const float*)d_in[16]; const float* b1 = (const float*)d_in[17];
    const float* W2 = (const float*)d_in[18]; const float* b2 = (const float*)d_in[19];
    const float* l2g = (const float*)d_in[20]; const float* l2b = (const float*)d_in[21];
    const float* pW = (const float*)d_in[22]; const float* pb = (const float*)d_in[23];
    float* out = (float*)d_out;

    float *h, *qkv, *tmp, *bqkv;
    __half *a3, *s2, *wqkv, *wo, *w1, *w2, *wp;
    cudaGetSymbolAddress((void**)&h, g_h);     cudaGetSymbolAddress((void**)&qkv, g_qkv);
    cudaGetSymbolAddress((void**)&tmp, g_tmp); cudaGetSymbolAddress((void**)&bqkv, g_bqkv);
    cudaGetSymbolAddress((void**)&a3, g_a3);   cudaGetSymbolAddress((void**)&s2, g_s2);
    cudaGetSymbolAddress((void**)&wqkv, g_wqkv); cudaGetSymbolAddress((void**)&wo, g_wo);
    cudaGetSymbolAddress((void**)&w1, g_w1);   cudaGetSymbolAddress((void**)&w2, g_w2);
    cudaGetSymbolAddress((void**)&wp, g_wp);

    const int smg = NSTG * STG + 128;
    cudaFuncSetAttribute(gemm_kernel, cudaFuncAttributeMaxDynamicSharedMemorySize, smg);
    cudaFuncSetAttribute(attn_kernel, cudaFuncAttributeMaxDynamicSharedMemorySize, ATTN_SMEM);

    // launch order chosen so index 3 (the ncu-captured launch) is the QKV GEMM
    embed_ln_kernel<<<TOK, 256>>>(x, len, tok, pos, leg, leb, h, a3);          // 0
    convert_qkv<<<dim3(D/32, D/32, 3), 256>>>(Wq, Wk, Wv, wqkv);               // 1
    concat_bias<<<4, 256>>>(bq, bk, bv, bqkv);                                 // 2
    gemm_kernel<<<dim3(TOK/128, K3D/128), 256, smg>>>(                         // 3  <-- profiled
        a3, wqkv, bqkv, qkv, (__half*)0, D, K3D, 0);

    convert_w<<<dim3(D/32, D/32), 256>>>(Wo, wo, D, D, 0);
    convert_w<<<dim3(D/32, FF/32), 256>>>(W1, w1, D, FF, 0);
    convert_w<<<dim3(FF/32, D/32), 256>>>(W2, w2, FF, D, 0);
    {
        size_t w = (size_t)D * D;
        convert_qkv<<<dim3(D/32, D/32, 3), 256>>>(Wq + w, Wk + w, Wv + w, wqkv + (size_t)K3D * D);
        convert_w<<<dim3(D/32, D/32), 256>>>(Wo + w, wo + (size_t)D*D, D, D, 0);
        convert_w<<<dim3(D/32, FF/32), 256>>>(W1 + (size_t)D*FF, w1 + (size_t)FF*D, D, FF, 0);
        convert_w<<<dim3(FF/32, D/32), 256>>>(W2 + (size_t)FF*D, w2 + (size_t)D*FF, FF, D, 0);
        concat_bias<<<4, 256>>>(bq + D, bk + D, bv + D, bqkv + K3D);
    }
    convert_w<<<dim3(D/32, V/32), 256>>>(pW, wp, D, V, 0);

    for (int i = 0; i < LYRS; i++) {
        if (i > 0)
            gemm_kernel<<<dim3(TOK/128, K3D/128), 256, smg>>>(
                a3, wqkv + (size_t)i*K3D*D, bqkv + (size_t)i*K3D, qkv, (__half*)0, D, K3D, 0);

        attn_kernel<<<dim3(SLEN/QT, H, BS), 128, ATTN_SMEM>>>(qkv, a3);

        gemm_kernel<<<dim3(TOK/128, D/128), 256, smg>>>(
            a3, wo + (size_t)i*D*D, bo + (size_t)i*D, tmp, (__half*)0, D, D, 0);
        add_ln_kernel<<<TOK, 256>>>(h, tmp, l1g + (size_t)i*D, l1b + (size_t)i*D, (const int*)0, h, a3);

        gemm_kernel<<<dim3(TOK/128, FF/128), 256, smg>>>(
            a3, w1 + (size_t)i*FF*D, b1 + (size_t)i*FF, (float*)0, s2, D, FF, 1);

        gemm_kernel<<<dim3(TOK/128, D/128), 256, smg>>>(
            s2, w2 + (size_t)i*D*FF, b2 + (size_t)i*D, tmp, (__half*)0, FF, D, 0);
        add_ln_kernel<<<TOK, 256>>>(h, tmp, l2g + (size_t)i*D, l2b + (size_t)i*D, len, h, a3);
    }

    gemm_kernel<<<dim3(TOK/128, V/128), 256, smg>>>(
        a3, wp, pb, out, (__half*)0, D, V, 0);
}

// round 15
// speedup vs baseline: 1.5248x; 1.3891x over previous
#include <cuda_runtime.h>
#include <cuda_fp16.h>
#include <math.h>
#include <stdint.h>

#define LYRS 2
#define H 16
#define D 1024
#define DH 64
#define FF 4096
#define V 32000
#define SLEN 1024
#define BS 2
#define TOK (BS*SLEN)
#define EPS 1e-12f
#define K3D (3*D)
#define NSTG 4
#define STG (3*8192)

// ---------------- scratch ----------------
__device__ float g_h  [TOK*D];
__device__ float g_qkv[TOK*K3D];
__device__ float g_tmp[TOK*D];
__device__ float g_bqkv[LYRS*K3D];
__device__ __align__(256) __half g_a3 [TOK*2*D];
__device__ __align__(256) __half g_s2 [TOK*2*FF];
__device__ __align__(256) __half g_wqkv[LYRS*(size_t)K3D*D];
__device__ __align__(256) __half g_wo  [LYRS*(size_t)D*D];
__device__ __align__(256) __half g_w1  [LYRS*(size_t)FF*D];
__device__ __align__(256) __half g_w2  [LYRS*(size_t)D*FF];
__device__ __align__(256) __half g_wp  [(size_t)V*D];

// ---------------- helpers ----------------
__device__ __forceinline__ uint32_t s2u(const void* p) {
    uint32_t a;
    asm("{ .reg .u64 t; cvta.to.shared.u64 t, %1; cvt.u32.u64 %0, t; }" : "=r"(a) : "l"(p));
    return a;
}
#define SWZ32(o) ((o) ^ (((o) >> 3) & 0x30))
__device__ __forceinline__ void mbar_init(uint32_t a, uint32_t c) {
    asm volatile("mbarrier.init.shared.b64 [%0], %1;" :: "r"(a), "r"(c) : "memory");
}
__device__ __forceinline__ void mbar_expect(uint32_t a, uint32_t tx) {
    asm volatile("mbarrier.arrive.expect_tx.shared.b64 _, [%0], %1;" :: "r"(a), "r"(tx) : "memory");
}
__device__ __forceinline__ void mbar_arrive(uint32_t a) {
    asm volatile("mbarrier.arrive.shared.b64 _, [%0];" :: "r"(a) : "memory");
}
__device__ __forceinline__ void mbar_wait(uint32_t a, uint32_t ph) {
    asm volatile(
        "{\n\t.reg .pred P;\n\tL_%=:\n\t"
        "mbarrier.try_wait.parity.acquire.cta.shared::cta.b64 P, [%0], %1, 0x989680;\n\t"
        "@P bra D_%=;\n\tbra L_%=;\n\tD_%=:\n\t}" :: "r"(a), "r"(ph) : "memory");
}
__device__ __forceinline__ void bulk_ld(uint32_t dst, const void* src, uint32_t bytes, uint32_t mbar) {
    asm volatile("cp.async.bulk.shared::cta.global.mbarrier::complete_tx::bytes [%0], [%1], %2, [%3];"
                 :: "r"(dst), "l"(src), "r"(bytes), "r"(mbar) : "memory");
}
__device__ __forceinline__ void ldm4(uint32_t (&r)[4], uint32_t addr) {
    asm volatile("ldmatrix.sync.aligned.m8n8.x4.shared.b16 {%0,%1,%2,%3}, [%4];"
                 : "=r"(r[0]), "=r"(r[1]), "=r"(r[2]), "=r"(r[3]) : "r"(addr));
}
__device__ __forceinline__ void mma16816(float (&c)[4], const uint32_t a0, const uint32_t a1,
                                         const uint32_t a2, const uint32_t a3,
                                         const uint32_t b0, const uint32_t b1) {
    asm volatile("mma.sync.aligned.m16n8k16.row.col.f32.f16.f16.f32 "
                 "{%0,%1,%2,%3}, {%4,%5,%6,%7}, {%8,%9}, {%0,%1,%2,%3};"
                 : "+f"(c[0]), "+f"(c[1]), "+f"(c[2]), "+f"(c[3])
                 : "r"(a0), "r"(a1), "r"(a2), "r"(a3), "r"(b0), "r"(b1));
}
__device__ __forceinline__ void split2(float v, __half& hi, __half& lo) {
    hi = __float2half(v);
    lo = __float2half(v - __half2float(hi));
}
__device__ __forceinline__ void store_elem(__half* buf, int nch, int row, int k, __half v) {
    int t = row >> 7, rr = row & 127, c = k >> 5, kk = k & 31;
    uint32_t off = SWZ32((uint32_t)(rr * 64 + kk * 2));
    *(__half*)((char*)buf + (((size_t)(t * nch + c)) << 13) + off) = v;
}

// ---------------- weight conversion (coalesced 16B swizzled stores) ----------------
__device__ __forceinline__ void conv_tile(const float* __restrict__ W, __half* __restrict__ out,
                                          int N, int nch, int k0, int n0, int rowOff) {
    __shared__ float t[32][33];
    __shared__ __half hb[32][40];
    int tx = threadIdx.x & 31, ty = threadIdx.x >> 5;
    #pragma unroll
    for (int i = 0; i < 4; i++)
        t[ty + i * 8][tx] = W[(size_t)(k0 + ty + i * 8) * N + n0 + tx];
    __syncthreads();
    #pragma unroll
    for (int i = 0; i < 4; i++)
        hb[ty + i * 8][tx] = __float2half(t[tx][ty + i * 8]);
    __syncthreads();
    if (threadIdx.x < 128) {
        int r = threadIdx.x >> 2, slot = threadIdx.x & 3;
        int n = rowOff + n0 + r;
        int tt = n >> 7, rr = n & 127;
        int sl = slot ^ ((rr >> 1) & 3);
        int4 v = *(int4*)&hb[r][slot * 8];
        *(int4*)((char*)out + (((size_t)(tt * nch + (k0 >> 5))) << 13) + rr * 64 + sl * 16) = v;
    }
}
__global__ void convert_w(const float* __restrict__ W, __half* __restrict__ out,
                          int K, int N, int rowOff) {
    conv_tile(W, out, N, K >> 5, blockIdx.x * 32, blockIdx.y * 32, rowOff);
}
__global__ void convert_qkv(const float* __restrict__ Wq, const float* __restrict__ Wk,
                            const float* __restrict__ Wv, __half* __restrict__ out) {
    const float* W = (blockIdx.z == 0) ? Wq : (blockIdx.z == 1) ? Wk : Wv;
    conv_tile(W, out, D, D >> 5, blockIdx.x * 32, blockIdx.y * 32, blockIdx.z * D);
}
__global__ void concat_bias(const float* __restrict__ a, const float* __restrict__ b,
                            const float* __restrict__ c, float* __restrict__ o) {
    int i = blockIdx.x * 256 + threadIdx.x;
    if (i < D) { o[i] = a[i]; o[D + i] = b[i]; o[2 * D + i] = c[i]; }
}

// ---------------- GEMM (producer/consumer, masked-tile skip) ----------------
__global__ void __launch_bounds__(256, 2) gemm_kernel(
    const __half* __restrict__ A, const __half* __restrict__ B,
    const float* __restrict__ bias, float* __restrict__ C, __half* __restrict__ S,
    int Kp, int N, int act, const int* __restrict__ lenp)
{
    extern __shared__ __align__(128) char smem[];
    const int tid = threadIdx.x, wid = tid >> 5, lane = tid & 31;
    const int wm = wid & 3, wn = wid >> 2;
    const int m0 = blockIdx.x * 128, n0 = blockIdx.y * 128;

    // dead-work skip: M-tile fully masked by lengths
    if (lenp && (m0 & 1023) >= lenp[m0 >> 10]) {
        if (C) {
            for (int idx = tid; idx < 128 * 32; idx += 256) {
                int r = idx >> 5, c4 = (idx & 31) * 4;
                float4 bv = *(const float4*)(bias + n0 + c4);
                *(float4*)(C + (size_t)(m0 + r) * N + n0 + c4) = bv;
            }
        }
        return;
    }

    const uint32_t sb = s2u(smem);
    const uint32_t FB = sb + NSTG * STG;
    const uint32_t EB = FB + NSTG * 8;
    const int nch0 = Kp / 32;

    if (tid == 0) {
        #pragma unroll
        for (int s = 0; s < NSTG; s++) { mbar_init(FB + 8 * s, 1); mbar_init(EB + 8 * s, 8); }
    }
    __syncthreads();

    auto issue = [&](int kk) {
        int s = kk & (NSTG - 1);
        uint32_t mb = FB + 8 * s, dst = sb + s * STG;
        mbar_expect(mb, 3 * 8192);
        bulk_ld(dst, (const char*)A + (((size_t)(blockIdx.x * 2 * nch0 + kk)) << 13), 8192, mb);
        bulk_ld(dst + 8192, (const char*)A + (((size_t)(blockIdx.x * 2 * nch0 + nch0 + kk)) << 13), 8192, mb);
        bulk_ld(dst + 16384, (const char*)B + (((size_t)(blockIdx.y * nch0 + kk)) << 13), 8192, mb);
    };
    if (tid == 0) { issue(0); issue(1); issue(2); }

    float acc[2][8][4];
    #pragma unroll
    for (int mi = 0; mi < 2; mi++)
        #pragma unroll
        for (int ni = 0; ni < 8; ni++)
            #pragma unroll
            for (int j = 0; j < 4; j++) acc[mi][ni][j] = 0.f;

    const int lq = lane & 7, lh = (lane >> 3) & 1, lk = lane >> 4;

    for (int kk = 0; kk < nch0; kk++) {
        int s = kk & (NSTG - 1);
        mbar_wait(FB + 8 * s, (kk >> 2) & 1);
        uint32_t stg = sb + s * STG;
        uint32_t bstg = stg + 16384;
        #pragma unroll
        for (int p = 0; p < 2; p++) {
            uint32_t astg = stg + p * 8192;
            #pragma unroll
            for (int ks = 0; ks < 2; ks++) {
                uint32_t af[2][4], bf[4][4];
                #pragma unroll
                for (int mt = 0; mt < 2; mt++) {
                    int r = wm * 32 + mt * 16 + lh * 8 + lq;
                    int sl = (ks * 2 + lk) ^ ((r >> 1) & 3);
                    ldm4(af[mt], astg + r * 64 + (sl << 4));
                }
                #pragma unroll
                for (int nt = 0; nt < 4; nt++) {
                    int r = wn * 64 + nt * 16 + lh * 8 + lq;
                    int sl = (ks * 2 + lk) ^ ((r >> 1) & 3);
                    ldm4(bf[nt], bstg + r * 64 + (sl << 4));
                }
                #pragma unroll
                for (int mi = 0; mi < 2; mi++)
                    #pragma unroll
                    for (int ni = 0; ni < 8; ni++) {
                        uint32_t b0 = bf[ni >> 1][ni & 1], b1 = bf[ni >> 1][(ni & 1) + 2];
                        mma16816(acc[mi][ni], af[mi][0], af[mi][1], af[mi][2], af[mi][3], b0, b1);
                    }
            }
        }
        if (lane == 0) mbar_arrive(EB + 8 * s);
        if (tid == 0) {
            int cc = kk + NSTG - 1;
            if (cc < nch0) {
                if (cc >= NSTG) mbar_wait(EB + 8 * (cc & (NSTG - 1)), ((cc >> 2) + 1) & 1);
                issue(cc);
            }
        }
    }

    const int r0 = lane >> 2, cp = (lane & 3) * 2;
    const int nchS = N >> 4;
    #pragma unroll
    for (int mi = 0; mi < 2; mi++) {
        #pragma unroll
        for (int ni = 0; ni < 8; ni++) {
            int col = n0 + wn * 64 + ni * 8 + cp;
            float bb0 = bias[col], bb1 = bias[col + 1];
            #pragma unroll
            for (int half = 0; half < 2; half++) {
                int row = m0 + wm * 32 + mi * 16 + r0 + half * 8;
                float v0 = acc[mi][ni][half * 2 + 0] + bb0;
                float v1 = acc[mi][ni][half * 2 + 1] + bb1;
                if (act) {
                    v0 = 0.5f * v0 * (1.0f + erff(v0 * 0.70710678118654752f));
                    v1 = 0.5f * v1 * (1.0f + erff(v1 * 0.70710678118654752f));
                }
                if (C) {
                    float2 o; o.x = v0; o.y = v1;
                    *(float2*)(C + (size_t)row * N + col) = o;
                }
                if (S) {
                    __half h0, l0, h1, l1;
                    split2(v0, h0, l0); split2(v1, h1, l1);
                    int t = row >> 7, rr = row & 127;
                    uint32_t off = SWZ32((uint32_t)(rr * 64 + (col & 31) * 2));
                    __half2 hp; hp.x = h0; hp.y = h1;
                    *(__half2*)((char*)S + (((size_t)(t * nchS + (col >> 5))) << 13) + off) = hp;
                    __half2 lp; lp.x = l0; lp.y = l1;
                    *(__half2*)((char*)S + (((size_t)(t * nchS + ((N + col) >> 5))) << 13) + off) = lp;
                }
            }
        }
    }
}

// ---------------- LayerNorm ----------------
__device__ __forceinline__ float brsum(float v, float* sbuf) {
    int tid = threadIdx.x;
    #pragma unroll
    for (int o = 16; o; o >>= 1) v += __shfl_down_sync(0xffffffffu, v, o);
    if ((tid & 31) == 0) sbuf[tid >> 5] = v;
    __syncthreads();
    if (tid < 8) {
        v = sbuf[tid];
        #pragma unroll
        for (int o = 4; o; o >>= 1) v += __shfl_down_sync(0xffu, v, o);
        if (tid == 0) sbuf[0] = v;
    }
    __syncthreads();
    float r = sbuf[0];
    __syncthreads();
    return r;
}
__global__ void embed_ln_kernel(const int* __restrict__ x, const int* __restrict__ len,
                                const float* __restrict__ tok, const float* __restrict__ pos,
                                const float* __restrict__ g, const float* __restrict__ b,
                                float* __restrict__ out, __half* __restrict__ sp) {
    int row = blockIdx.x, bi = row / SLEN, s = row % SLEN, token = x[row], tid = threadIdx.x;
    __shared__ float buf[D]; __shared__ float red[8];
    float ls = 0.f;
    #pragma unroll
    for (int i = 0; i < 4; i++) {
        int c = tid + i * 256;
        float v = tok[(size_t)token * D + c] + pos[(size_t)s * D + c];
        buf[c] = v; ls += v;
    }
    float mean = brsum(ls, red) * (1.0f / D), ss = 0.f;
    #pragma unroll
    for (int i = 0; i < 4; i++) { float d = buf[tid + i * 256] - mean; ss += d * d; }
    float rstd = rsqrtf(brsum(ss, red) * (1.0f / D) + EPS);
    float mask = (s < len[bi]) ? 1.0f : 0.0f;
    #pragma unroll
    for (int i = 0; i < 4; i++) {
        int c = tid + i * 256;
        float v = (g[c] * (buf[c] - mean) * rstd + b[c]) * mask;
        out[(size_t)row * D + c] = v;
        __half hi, lo; split2(v, hi, lo);
        store_elem(sp, 64, row, c, hi);
        store_elem(sp, 64, row, D + c, lo);
    }
}
__global__ void add_ln_kernel(const float* __restrict__ a, const float* __restrict__ dl,
                              const float* __restrict__ g, const float* __restrict__ b,
                              const int* __restrict__ len, float* __restrict__ out,
                              __half* __restrict__ sp) {
    int row = blockIdx.x, bi = row / SLEN, s = row % SLEN, tid = threadIdx.x;
    __shared__ float buf[D]; __shared__ float red[8];
    float ls = 0.f;
    #pragma unroll
    for (int i = 0; i < 4; i++) {
        int c = tid + i * 256;
        float v = a[(size_t)row * D + c] + dl[(size_t)row * D + c];
        buf[c] = v; ls += v;
    }
    float mean = brsum(ls, red) * (1.0f / D), ss = 0.f;
    #pragma unroll
    for (int i = 0; i < 4; i++) { float d = buf[tid + i * 256] - mean; ss += d * d; }
    float rstd = rsqrtf(brsum(ss, red) * (1.0f / D) + EPS);
    float mask = len ? ((s < len[bi]) ? 1.0f : 0.0f) : 1.0f;
    #pragma unroll
    for (int i = 0; i < 4; i++) {
        int c = tid + i * 256;
        float v = (g[c] * (buf[c] - mean) * rstd + b[c]) * mask;
        out[(size_t)row * D + c] = v;
        __half hi, lo; split2(v, hi, lo);
        store_elem(sp, 64, row, c, hi);
        store_elem(sp, 64, row, D + c, lo);
    }
}

// ---------------- attention: masked q-blocks skipped ----------------
#define QT 8
#define KCH 128
#define ATTN_SMEM ((QT*DH + QT*SLEN + KCH*65 + QT) * 4)
__global__ void attn_kernel(const float* __restrict__ qkv, __half* __restrict__ a3,
                            const int* __restrict__ lenp) {
    const int q0 = blockIdx.x * QT, hd = blockIdx.y, bb = blockIdx.z, tid = threadIdx.x;
    if (q0 >= lenp[bb]) return;   // all queries masked -> outputs dead
    extern __shared__ float sm[];
    float* sq = sm;
    float* sc = sq + QT * DH;
    float* sk = sc + QT * SLEN;
    float* sinv = sk + KCH * 65;
    const int wid = tid >> 5, lane = tid & 31;
    const int nkb = q0 + QT;
    const size_t rb = (size_t)(bb * SLEN) * K3D + (size_t)hd * DH;

    for (int i = tid; i < QT * DH; i += 128)
        sq[i] = qkv[rb + (size_t)(q0 + i / DH) * K3D + (i % DH)] * 0.125f;
    __syncthreads();

    const float* kb = qkv + rb + D;
    for (int c0 = 0; c0 < nkb; c0 += KCH) {
        int rows = nkb - c0; if (rows > KCH) rows = KCH;
        for (int idx = tid; idx < rows * 16; idx += 128) {
            int r = idx >> 4, c4 = (idx & 15) * 4;
            float4 v = *(const float4*)(kb + (size_t)(c0 + r) * K3D + c4);
            sk[r * 65 + c4 + 0] = v.x; sk[r * 65 + c4 + 1] = v.y;
            sk[r * 65 + c4 + 2] = v.z; sk[r * 65 + c4 + 3] = v.w;
        }
        __syncthreads();
        for (int key = tid; key < rows; key += 128) {
            float a[QT];
            #pragma unroll
            for (int qi = 0; qi < QT; qi++) a[qi] = 0.f;
            #pragma unroll 8
            for (int d = 0; d < DH; d++) {
                float kd = sk[key * 65 + d];
                #pragma unroll
                for (int qi = 0; qi < QT; qi++) a[qi] = fmaf(sq[qi * DH + d], kd, a[qi]);
            }
            #pragma unroll
            for (int qi = 0; qi < QT; qi++) sc[qi * SLEN + c0 + key] = a[qi];
        }
        __syncthreads();
    }

    #pragma unroll
    for (int t = 0; t < 2; t++) {
        int qi = wid * 2 + t, bound = q0 + qi;
        float mx = -1e30f;
        for (int key = lane; key <= bound; key += 32) mx = fmaxf(mx, sc[qi * SLEN + key]);
        #pragma unroll
        for (int o = 16; o; o >>= 1) mx = fmaxf(mx, __shfl_xor_sync(0xffffffffu, mx, o));
        float s = 0.f;
        for (int key = lane; key < nkb; key += 32) {
            float e = (key <= bound) ? expf(sc[qi * SLEN + key] - mx) : 0.f;
            sc[qi * SLEN + key] = e; s += e;
        }
        #pragma unroll
        for (int o = 16; o; o >>= 1) s += __shfl_xor_sync(0xffffffffu, s, o);
        if (lane == 0) sinv[qi] = 1.0f / s;
    }
    __syncthreads();

    const int d = tid & 63, half = tid >> 6;
    const float* vb = qkv + rb + 2 * D;
    float a[QT];
    #pragma unroll
    for (int qi = 0; qi < QT; qi++) a[qi] = 0.f;
    for (int c0 = 0; c0 < nkb; c0 += KCH) {
        int rows = nkb - c0; if (rows > KCH) rows = KCH;
        for (int idx = tid; idx < rows * 16; idx += 128) {
            int r = idx >> 4, c4 = (idx & 15) * 4;
            float4 v = *(const float4*)(vb + (size_t)(c0 + r) * K3D + c4);
            sk[r * 65 + c4 + 0] = v.x; sk[r * 65 + c4 + 1] = v.y;
            sk[r * 65 + c4 + 2] = v.z; sk[r * 65 + c4 + 3] = v.w;
        }
        __syncthreads();
        for (int key = half; key < rows; key += 2) {
            float vv = sk[key * 65 + d];
            #pragma unroll
            for (int qi = 0; qi < QT; qi++)
                a[qi] = fmaf(sc[qi * SLEN + c0 + key], vv, a[qi]);
        }
        __syncthreads();
    }
    for (int qi = 0; qi < QT; qi++) {
        sk[tid] = a[qi]; __syncthreads();
        if (tid < 64) {
            float v = (sk[tid] + sk[tid + 64]) * sinv[qi];
            int row = bb * SLEN + q0 + qi;
            __half hi, lo; split2(v, hi, lo);
            store_elem(a3, 64, row, hd * DH + d, hi);
            store_elem(a3, 64, row, D + hd * DH + d, lo);
        }
        __syncthreads();
    }
}

// ---------------- launcher ----------------
extern "C" void kernel_launch(void* const* d_in, const int* in_sizes, int n_in,
                              void* d_out, int out_size) {
    const int*   x   = (const int*)  d_in[0];
    const int*   len = (const int*)  d_in[1];
    const float* tok = (const float*)d_in[2];
    const float* pos = (const float*)d_in[3];
    const float* leg = (const float*)d_in[4];
    const float* leb = (const float*)d_in[5];
    const float* Wq = (const float*)d_in[6];  const float* bq = (const float*)d_in[7];
    const float* Wk = (const float*)d_in[8];  const float* bk = (const float*)d_in[9];
    const float* Wv = (const float*)d_in[10]; const float* bv = (const float*)d_in[11];
    const float* Wo = (const float*)d_in[12]; const float* bo = (const float*)d_in[13];
    const float* l1g = (const float*)d_in[14]; const float* l1b = (const float*)d_in[15];
    const float* W1 = (const float*)d_in[16]; const float* b1 = (const float*)d_in[17];
    const float* W2 = (const float*)d_in[18]; const float* b2 = (const float*)d_in[19];
    const float* l2g = (const float*)d_in[20]; const float* l2b = (const float*)d_in[21];
    const float* pW = (const float*)d_in[22]; const float* pb = (const float*)d_in[23];
    float* out = (float*)d_out;

    float *h, *qkv, *tmp, *bqkv;
    __half *a3, *s2, *wqkv, *wo, *w1, *w2, *wp;
    cudaGetSymbolAddress((void**)&h, g_h);     cudaGetSymbolAddress((void**)&qkv, g_qkv);
    cudaGetSymbolAddress((void**)&tmp, g_tmp); cudaGetSymbolAddress((void**)&bqkv, g_bqkv);
    cudaGetSymbolAddress((void**)&a3, g_a3);   cudaGetSymbolAddress((void**)&s2, g_s2);
    cudaGetSymbolAddress((void**)&wqkv, g_wqkv); cudaGetSymbolAddress((void**)&wo, g_wo);
    cudaGetSymbolAddress((void**)&w1, g_w1);   cudaGetSymbolAddress((void**)&w2, g_w2);
    cudaGetSymbolAddress((void**)&wp, g_wp);

    const int smg = NSTG * STG + 128;
    cudaFuncSetAttribute(gemm_kernel, cudaFuncAttributeMaxDynamicSharedMemorySize, smg);
    cudaFuncSetAttribute(attn_kernel, cudaFuncAttributeMaxDynamicSharedMemorySize, ATTN_SMEM);

    // launch order: index 3 (ncu-captured) is the QKV GEMM
    embed_ln_kernel<<<TOK, 256>>>(x, len, tok, pos, leg, leb, h, a3);          // 0
    convert_qkv<<<dim3(D/32, D/32, 3), 256>>>(Wq, Wk, Wv, wqkv);               // 1
    concat_bias<<<4, 256>>>(bq, bk, bv, bqkv);                                 // 2
    gemm_kernel<<<dim3(TOK/128, K3D/128), 256, smg>>>(                         // 3
        a3, wqkv, bqkv, qkv, (__half*)0, D, K3D, 0, len);

    convert_w<<<dim3(D/32, D/32), 256>>>(Wo, wo, D, D, 0);
    convert_w<<<dim3(D/32, FF/32), 256>>>(W1, w1, D, FF, 0);
    convert_w<<<dim3(FF/32, D/32), 256>>>(W2, w2, FF, D, 0);
    {
        size_t w = (size_t)D * D;
        convert_qkv<<<dim3(D/32, D/32, 3), 256>>>(Wq + w, Wk + w, Wv + w, wqkv + (size_t)K3D * D);
        convert_w<<<dim3(D/32, D/32), 256>>>(Wo + w, wo + (size_t)D*D, D, D, 0);
        convert_w<<<dim3(D/32, FF/32), 256>>>(W1 + (size_t)D*FF, w1 + (size_t)FF*D, D, FF, 0);
        convert_w<<<dim3(FF/32, D/32), 256>>>(W2 + (size_t)FF*D, w2 + (size_t)D*FF, FF, D, 0);
        concat_bias<<<4, 256>>>(bq + D, bk + D, bv + D, bqkv + K3D);
    }
    convert_w<<<dim3(D/32, V/32), 256>>>(pW, wp, D, V, 0);

    for (int i = 0; i < LYRS; i++) {
        if (i > 0)
            gemm_kernel<<<dim3(TOK/128, K3D/128), 256, smg>>>(
                a3, wqkv + (size_t)i*K3D*D, bqkv + (size_t)i*K3D, qkv, (__half*)0, D, K3D, 0, len);

        attn_kernel<<<dim3(SLEN/QT, H, BS), 128, ATTN_SMEM>>>(qkv, a3, len);

        gemm_kernel<<<dim3(TOK/128, D/128), 256, smg>>>(
            a3, wo + (size_t)i*D*D, bo + (size_t)i*D, tmp, (__half*)0, D, D, 0, len);
        add_ln_kernel<<<TOK, 256>>>(h, tmp, l1g + (size_t)i*D, l1b + (size_t)i*D, (const int*)0, h, a3);

        gemm_kernel<<<dim3(TOK/128, FF/128), 256, smg>>>(
            a3, w1 + (size_t)i*FF*D, b1 + (size_t)i*FF, (float*)0, s2, D, FF, 1, len);

        gemm_kernel<<<dim3(TOK/128, D/128), 256, smg>>>(
            s2, w2 + (size_t)i*D*FF, b2 + (size_t)i*D, tmp, (__half*)0, FF, D, 0, len);
        add_ln_kernel<<<TOK, 256>>>(h, tmp, l2g + (size_t)i*D, l2b + (size_t)i*D, len, h, a3);
    }

    gemm_kernel<<<dim3(TOK/128, V/128), 256, smg>>>(
        a3, wp, pb, out, (__half*)0, D, V, 0, len);
}

// round 16
// speedup vs baseline: 1.5821x; 1.0376x over previous
#include <cuda_runtime.h>
#include <cuda_fp16.h>
#include <math.h>
#include <stdint.h>

#define LYRS 2
#define H 16
#define D 1024
#define DH 64
#define FF 4096
#define V 32000
#define SLEN 1024
#define BS 2
#define TOK (BS*SLEN)
#define EPS 1e-12f
#define K3D (3*D)
#define NSTG 4
#define STG (3*8192)

// ---------------- scratch ----------------
__device__ float g_h  [TOK*D];
__device__ float g_qkv[TOK*K3D];
__device__ float g_tmp[TOK*D];
__device__ float g_bqkv[LYRS*K3D];
__device__ __align__(256) __half g_a3 [TOK*2*D];
__device__ __align__(256) __half g_s2 [TOK*2*FF];
__device__ __align__(256) __half g_wqkv[LYRS*(size_t)K3D*D];
__device__ __align__(256) __half g_wo  [LYRS*(size_t)D*D];
__device__ __align__(256) __half g_w1  [LYRS*(size_t)FF*D];
__device__ __align__(256) __half g_w2  [LYRS*(size_t)D*FF];
__device__ __align__(256) __half g_wp  [(size_t)V*D];

// ---------------- helpers ----------------
__device__ __forceinline__ uint32_t s2u(const void* p) {
    uint32_t a;
    asm("{ .reg .u64 t; cvta.to.shared.u64 t, %1; cvt.u32.u64 %0, t; }" : "=r"(a) : "l"(p));
    return a;
}
#define SWZ32(o) ((o) ^ (((o) >> 3) & 0x30))
__device__ __forceinline__ void mbar_init(uint32_t a, uint32_t c) {
    asm volatile("mbarrier.init.shared.b64 [%0], %1;" :: "r"(a), "r"(c) : "memory");
}
__device__ __forceinline__ void mbar_expect(uint32_t a, uint32_t tx) {
    asm volatile("mbarrier.arrive.expect_tx.shared.b64 _, [%0], %1;" :: "r"(a), "r"(tx) : "memory");
}
__device__ __forceinline__ void mbar_arrive(uint32_t a) {
    asm volatile("mbarrier.arrive.shared.b64 _, [%0];" :: "r"(a) : "memory");
}
__device__ __forceinline__ void mbar_wait(uint32_t a, uint32_t ph) {
    asm volatile(
        "{\n\t.reg .pred P;\n\tL_%=:\n\t"
        "mbarrier.try_wait.parity.acquire.cta.shared::cta.b64 P, [%0], %1, 0x989680;\n\t"
        "@P bra D_%=;\n\tbra L_%=;\n\tD_%=:\n\t}" :: "r"(a), "r"(ph) : "memory");
}
__device__ __forceinline__ void bulk_ld(uint32_t dst, const void* src, uint32_t bytes, uint32_t mbar) {
    asm volatile("cp.async.bulk.shared::cta.global.mbarrier::complete_tx::bytes [%0], [%1], %2, [%3];"
                 :: "r"(dst), "l"(src), "r"(bytes), "r"(mbar) : "memory");
}
__device__ __forceinline__ void ldm4(uint32_t (&r)[4], uint32_t addr) {
    asm volatile("ldmatrix.sync.aligned.m8n8.x4.shared.b16 {%0,%1,%2,%3}, [%4];"
                 : "=r"(r[0]), "=r"(r[1]), "=r"(r[2]), "=r"(r[3]) : "r"(addr));
}
__device__ __forceinline__ void mma16816(float (&c)[4], const uint32_t a0, const uint32_t a1,
                                         const uint32_t a2, const uint32_t a3,
                                         const uint32_t b0, const uint32_t b1) {
    asm volatile("mma.sync.aligned.m16n8k16.row.col.f32.f16.f16.f32 "
                 "{%0,%1,%2,%3}, {%4,%5,%6,%7}, {%8,%9}, {%0,%1,%2,%3};"
                 : "+f"(c[0]), "+f"(c[1]), "+f"(c[2]), "+f"(c[3])
                 : "r"(a0), "r"(a1), "r"(a2), "r"(a3), "r"(b0), "r"(b1));
}
__device__ __forceinline__ void split2(float v, __half& hi, __half& lo) {
    hi = __float2half(v);
    lo = __float2half(v - __half2float(hi));
}
__device__ __forceinline__ void store_elem(__half* buf, int nch, int row, int k, __half v) {
    int t = row >> 7, rr = row & 127, c = k >> 5, kk = k & 31;
    uint32_t off = SWZ32((uint32_t)(rr * 64 + kk * 2));
    *(__half*)((char*)buf + (((size_t)(t * nch + c)) << 13) + off) = v;
}

// ---------------- weight conversion (coalesced 16B swizzled stores) ----------------
__device__ __forceinline__ void conv_tile(const float* __restrict__ W, __half* __restrict__ out,
                                          int N, int nch, int k0, int n0, int rowOff) {
    __shared__ float t[32][33];
    __shared__ __half hb[32][40];
    int tx = threadIdx.x & 31, ty = threadIdx.x >> 5;
    #pragma unroll
    for (int i = 0; i < 4; i++)
        t[ty + i * 8][tx] = W[(size_t)(k0 + ty + i * 8) * N + n0 + tx];
    __syncthreads();
    #pragma unroll
    for (int i = 0; i < 4; i++)
        hb[ty + i * 8][tx] = __float2half(t[tx][ty + i * 8]);
    __syncthreads();
    if (threadIdx.x < 128) {
        int r = threadIdx.x >> 2, slot = threadIdx.x & 3;
        int n = rowOff + n0 + r;
        int tt = n >> 7, rr = n & 127;
        int sl = slot ^ ((rr >> 1) & 3);
        int4 v = *(int4*)&hb[r][slot * 8];
        *(int4*)((char*)out + (((size_t)(tt * nch + (k0 >> 5))) << 13) + rr * 64 + sl * 16) = v;
    }
}
__global__ void convert_w(const float* __restrict__ W, __half* __restrict__ out,
                          int K, int N, int rowOff) {
    conv_tile(W, out, N, K >> 5, blockIdx.x * 32, blockIdx.y * 32, rowOff);
}
__global__ void convert_qkv(const float* __restrict__ Wq, const float* __restrict__ Wk,
                            const float* __restrict__ Wv, __half* __restrict__ out) {
    const float* W = (blockIdx.z == 0) ? Wq : (blockIdx.z == 1) ? Wk : Wv;
    conv_tile(W, out, D, D >> 5, blockIdx.x * 32, blockIdx.y * 32, blockIdx.z * D);
}
__global__ void concat_bias(const float* __restrict__ a, const float* __restrict__ b,
                            const float* __restrict__ c, float* __restrict__ o) {
    int i = blockIdx.x * 256 + threadIdx.x;
    if (i < D) { o[i] = a[i]; o[D + i] = b[i]; o[2 * D + i] = c[i]; }
}

// ---------------- GEMM (producer/consumer, masked-tile skip) ----------------
__global__ void __launch_bounds__(256, 2) gemm_kernel(
    const __half* __restrict__ A, const __half* __restrict__ B,
    const float* __restrict__ bias, float* __restrict__ C, __half* __restrict__ S,
    int Kp, int N, int act, const int* __restrict__ lenp)
{
    extern __shared__ __align__(128) char smem[];
    const int tid = threadIdx.x, wid = tid >> 5, lane = tid & 31;
    const int wm = wid & 3, wn = wid >> 2;
    const int m0 = blockIdx.x * 128, n0 = blockIdx.y * 128;

    if (lenp && (m0 & 1023) >= lenp[m0 >> 10]) {
        if (C) {
            for (int idx = tid; idx < 128 * 32; idx += 256) {
                int r = idx >> 5, c4 = (idx & 31) * 4;
                float4 bv = *(const float4*)(bias + n0 + c4);
                *(float4*)(C + (size_t)(m0 + r) * N + n0 + c4) = bv;
            }
        }
        return;
    }

    const uint32_t sb = s2u(smem);
    const uint32_t FB = sb + NSTG * STG;
    const uint32_t EB = FB + NSTG * 8;
    const int nch0 = Kp / 32;

    if (tid == 0) {
        #pragma unroll
        for (int s = 0; s < NSTG; s++) { mbar_init(FB + 8 * s, 1); mbar_init(EB + 8 * s, 8); }
    }
    __syncthreads();

    auto issue = [&](int kk) {
        int s = kk & (NSTG - 1);
        uint32_t mb = FB + 8 * s, dst = sb + s * STG;
        mbar_expect(mb, 3 * 8192);
        bulk_ld(dst, (const char*)A + (((size_t)(blockIdx.x * 2 * nch0 + kk)) << 13), 8192, mb);
        bulk_ld(dst + 8192, (const char*)A + (((size_t)(blockIdx.x * 2 * nch0 + nch0 + kk)) << 13), 8192, mb);
        bulk_ld(dst + 16384, (const char*)B + (((size_t)(blockIdx.y * nch0 + kk)) << 13), 8192, mb);
    };
    if (tid == 0) { issue(0); issue(1); issue(2); }

    float acc[2][8][4];
    #pragma unroll
    for (int mi = 0; mi < 2; mi++)
        #pragma unroll
        for (int ni = 0; ni < 8; ni++)
            #pragma unroll
            for (int j = 0; j < 4; j++) acc[mi][ni][j] = 0.f;

    const int lq = lane & 7, lh = (lane >> 3) & 1, lk = lane >> 4;

    for (int kk = 0; kk < nch0; kk++) {
        int s = kk & (NSTG - 1);
        mbar_wait(FB + 8 * s, (kk >> 2) & 1);
        uint32_t stg = sb + s * STG;
        uint32_t bstg = stg + 16384;
        #pragma unroll
        for (int p = 0; p < 2; p++) {
            uint32_t astg = stg + p * 8192;
            #pragma unroll
            for (int ks = 0; ks < 2; ks++) {
                uint32_t af[2][4], bf[4][4];
                #pragma unroll
                for (int mt = 0; mt < 2; mt++) {
                    int r = wm * 32 + mt * 16 + lh * 8 + lq;
                    int sl = (ks * 2 + lk) ^ ((r >> 1) & 3);
                    ldm4(af[mt], astg + r * 64 + (sl << 4));
                }
                #pragma unroll
                for (int nt = 0; nt < 4; nt++) {
                    int r = wn * 64 + nt * 16 + lh * 8 + lq;
                    int sl = (ks * 2 + lk) ^ ((r >> 1) & 3);
                    ldm4(bf[nt], bstg + r * 64 + (sl << 4));
                }
                #pragma unroll
                for (int mi = 0; mi < 2; mi++)
                    #pragma unroll
                    for (int ni = 0; ni < 8; ni++) {
                        uint32_t b0 = bf[ni >> 1][ni & 1], b1 = bf[ni >> 1][(ni & 1) + 2];
                        mma16816(acc[mi][ni], af[mi][0], af[mi][1], af[mi][2], af[mi][3], b0, b1);
                    }
            }
        }
        if (lane == 0) mbar_arrive(EB + 8 * s);
        if (tid == 0) {
            int cc = kk + NSTG - 1;
            if (cc < nch0) {
                if (cc >= NSTG) mbar_wait(EB + 8 * (cc & (NSTG - 1)), ((cc >> 2) + 1) & 1);
                issue(cc);
            }
        }
    }

    const int r0 = lane >> 2, cp = (lane & 3) * 2;
    const int nchS = N >> 4;
    #pragma unroll
    for (int mi = 0; mi < 2; mi++) {
        #pragma unroll
        for (int ni = 0; ni < 8; ni++) {
            int col = n0 + wn * 64 + ni * 8 + cp;
            float bb0 = bias[col], bb1 = bias[col + 1];
            #pragma unroll
            for (int half = 0; half < 2; half++) {
                int row = m0 + wm * 32 + mi * 16 + r0 + half * 8;
                float v0 = acc[mi][ni][half * 2 + 0] + bb0;
                float v1 = acc[mi][ni][half * 2 + 1] + bb1;
                if (act) {
                    v0 = 0.5f * v0 * (1.0f + erff(v0 * 0.70710678118654752f));
                    v1 = 0.5f * v1 * (1.0f + erff(v1 * 0.70710678118654752f));
                }
                if (C) {
                    float2 o; o.x = v0; o.y = v1;
                    *(float2*)(C + (size_t)row * N + col) = o;
                }
                if (S) {
                    __half h0, l0, h1, l1;
                    split2(v0, h0, l0); split2(v1, h1, l1);
                    int t = row >> 7, rr = row & 127;
                    uint32_t off = SWZ32((uint32_t)(rr * 64 + (col & 31) * 2));
                    __half2 hp; hp.x = h0; hp.y = h1;
                    *(__half2*)((char*)S + (((size_t)(t * nchS + (col >> 5))) << 13) + off) = hp;
                    __half2 lp; lp.x = l0; lp.y = l1;
                    *(__half2*)((char*)S + (((size_t)(t * nchS + ((N + col) >> 5))) << 13) + off) = lp;
                }
            }
        }
    }
}

// ---------------- LayerNorm ----------------
__device__ __forceinline__ float brsum(float v, float* sbuf) {
    int tid = threadIdx.x;
    #pragma unroll
    for (int o = 16; o; o >>= 1) v += __shfl_down_sync(0xffffffffu, v, o);
    if ((tid & 31) == 0) sbuf[tid >> 5] = v;
    __syncthreads();
    if (tid < 8) {
        v = sbuf[tid];
        #pragma unroll
        for (int o = 4; o; o >>= 1) v += __shfl_down_sync(0xffu, v, o);
        if (tid == 0) sbuf[0] = v;
    }
    __syncthreads();
    float r = sbuf[0];
    __syncthreads();
    return r;
}
__device__ __forceinline__ void ln_zero_row(float* out, __half* sp, int row, int tid) {
    #pragma unroll
    for (int i = 0; i < 4; i++) {
        int c = tid + i * 256;
        out[(size_t)row * D + c] = 0.f;
        store_elem(sp, 64, row, c, __float2half(0.f));
        store_elem(sp, 64, row, D + c, __float2half(0.f));
    }
}
__global__ void embed_ln_kernel(const int* __restrict__ x, const int* __restrict__ len,
                                const float* __restrict__ tok, const float* __restrict__ pos,
                                const float* __restrict__ g, const float* __restrict__ b,
                                float* __restrict__ out, __half* __restrict__ sp) {
    int row = blockIdx.x, bi = row / SLEN, s = row % SLEN, tid = threadIdx.x;
    if (s >= len[bi]) { ln_zero_row(out, sp, row, tid); return; }
    int token = x[row];
    __shared__ float buf[D]; __shared__ float red[8];
    float ls = 0.f;
    #pragma unroll
    for (int i = 0; i < 4; i++) {
        int c = tid + i * 256;
        float v = tok[(size_t)token * D + c] + pos[(size_t)s * D + c];
        buf[c] = v; ls += v;
    }
    float mean = brsum(ls, red) * (1.0f / D), ss = 0.f;
    #pragma unroll
    for (int i = 0; i < 4; i++) { float d = buf[tid + i * 256] - mean; ss += d * d; }
    float rstd = rsqrtf(brsum(ss, red) * (1.0f / D) + EPS);
    #pragma unroll
    for (int i = 0; i < 4; i++) {
        int c = tid + i * 256;
        float v = g[c] * (buf[c] - mean) * rstd + b[c];
        out[(size_t)row * D + c] = v;
        __half hi, lo; split2(v, hi, lo);
        store_elem(sp, 64, row, c, hi);
        store_elem(sp, 64, row, D + c, lo);
    }
}
__global__ void add_ln_kernel(const float* __restrict__ a, const float* __restrict__ dl,
                              const float* __restrict__ g, const float* __restrict__ b,
                              const int* __restrict__ len, float* __restrict__ out,
                              __half* __restrict__ sp) {
    int row = blockIdx.x, bi = row / SLEN, s = row % SLEN, tid = threadIdx.x;
    if (len && s >= len[bi]) { ln_zero_row(out, sp, row, tid); return; }
    __shared__ float buf[D]; __shared__ float red[8];
    float ls = 0.f;
    #pragma unroll
    for (int i = 0; i < 4; i++) {
        int c = tid + i * 256;
        float v = a[(size_t)row * D + c] + dl[(size_t)row * D + c];
        buf[c] = v; ls += v;
    }
    float mean = brsum(ls, red) * (1.0f / D), ss = 0.f;
    #pragma unroll
    for (int i = 0; i < 4; i++) { float d = buf[tid + i * 256] - mean; ss += d * d; }
    float rstd = rsqrtf(brsum(ss, red) * (1.0f / D) + EPS);
    #pragma unroll
    for (int i = 0; i < 4; i++) {
        int c = tid + i * 256;
        float v = g[c] * (buf[c] - mean) * rstd + b[c];
        out[(size_t)row * D + c] = v;
        __half hi, lo; split2(v, hi, lo);
        store_elem(sp, 64, row, c, hi);
        store_elem(sp, 64, row, D + c, lo);
    }
}

// ---------------- attention: 16 q/block, 256 threads ----------------
#define QT 16
#define KCH 128
#define ATTN_SMEM ((QT*DH + QT*SLEN + KCH*65 + QT) * 4)
__global__ void __launch_bounds__(256) attn_kernel(const float* __restrict__ qkv,
                                                   __half* __restrict__ a3,
                                                   const int* __restrict__ lenp) {
    const int q0 = blockIdx.x * QT, hd = blockIdx.y, bb = blockIdx.z, tid = threadIdx.x;
    if (q0 >= lenp[bb]) return;
    extern __shared__ float sm[];
    float* sq = sm;                        // QT*64
    float* sc = sq + QT * DH;              // QT*1024
    float* sk = sc + QT * SLEN;            // 128*65
    float* sinv = sk + KCH * 65;           // QT
    const int wid = tid >> 5, lane = tid & 31;
    const int nkb = q0 + QT;
    const size_t rb = (size_t)(bb * SLEN) * K3D + (size_t)hd * DH;

    for (int i = tid; i < QT * DH; i += 256)
        sq[i] = qkv[rb + (size_t)(q0 + i / DH) * K3D + (i % DH)] * 0.125f;
    __syncthreads();

    const float* kb = qkv + rb + D;
    for (int c0 = 0; c0 < nkb; c0 += KCH) {
        int rows = nkb - c0; if (rows > KCH) rows = KCH;
        for (int idx = tid; idx < rows * 16; idx += 256) {
            int r = idx >> 4, c4 = (idx & 15) * 4;
            float4 v = *(const float4*)(kb + (size_t)(c0 + r) * K3D + c4);
            sk[r * 65 + c4 + 0] = v.x; sk[r * 65 + c4 + 1] = v.y;
            sk[r * 65 + c4 + 2] = v.z; sk[r * 65 + c4 + 3] = v.w;
        }
        __syncthreads();
        for (int key = tid; key < rows; key += 256) {
            float a[QT];
            #pragma unroll
            for (int qi = 0; qi < QT; qi++) a[qi] = 0.f;
            #pragma unroll 8
            for (int d = 0; d < DH; d++) {
                float kd = sk[key * 65 + d];
                #pragma unroll
                for (int qi = 0; qi < QT; qi++) a[qi] = fmaf(sq[qi * DH + d], kd, a[qi]);
            }
            #pragma unroll
            for (int qi = 0; qi < QT; qi++) sc[qi * SLEN + c0 + key] = a[qi];
        }
        __syncthreads();
    }

    #pragma unroll
    for (int t = 0; t < 2; t++) {
        int qi = wid * 2 + t, bound = q0 + qi;
        float mx = -1e30f;
        for (int key = lane; key <= bound; key += 32) mx = fmaxf(mx, sc[qi * SLEN + key]);
        #pragma unroll
        for (int o = 16; o; o >>= 1) mx = fmaxf(mx, __shfl_xor_sync(0xffffffffu, mx, o));
        float s = 0.f;
        for (int key = lane; key < nkb; key += 32) {
            float e = (key <= bound) ? expf(sc[qi * SLEN + key] - mx) : 0.f;
            sc[qi * SLEN + key] = e; s += e;
        }
        #pragma unroll
        for (int o = 16; o; o >>= 1) s += __shfl_xor_sync(0xffffffffu, s, o);
        if (lane == 0) sinv[qi] = 1.0f / s;
    }
    __syncthreads();

    const int d = tid & 63, q4 = tid >> 6;   // 4 partitions over keys
    const float* vb = qkv + rb + 2 * D;
    float a[QT];
    #pragma unroll
    for (int qi = 0; qi < QT; qi++) a[qi] = 0.f;
    for (int c0 = 0; c0 < nkb; c0 += KCH) {
        int rows = nkb - c0; if (rows > KCH) rows = KCH;
        for (int idx = tid; idx < rows * 16; idx += 256) {
            int r = idx >> 4, c4 = (idx & 15) * 4;
            float4 v = *(const float4*)(vb + (size_t)(c0 + r) * K3D + c4);
            sk[r * 65 + c4 + 0] = v.x; sk[r * 65 + c4 + 1] = v.y;
            sk[r * 65 + c4 + 2] = v.z; sk[r * 65 + c4 + 3] = v.w;
        }
        __syncthreads();
        for (int key = q4; key < rows; key += 4) {
            float vv = sk[key * 65 + d];
            #pragma unroll
            for (int qi = 0; qi < QT; qi++)
                a[qi] = fmaf(sc[qi * SLEN + c0 + key], vv, a[qi]);
        }
        __syncthreads();
    }
    for (int qi = 0; qi < QT; qi++) {
        sk[tid] = a[qi]; __syncthreads();
        if (tid < 64) {
            float v = (sk[tid] + sk[tid + 64] + sk[tid + 128] + sk[tid + 192]) * sinv[qi];
            int row = bb * SLEN + q0 + qi;
            __half hi, lo; split2(v, hi, lo);
            store_elem(a3, 64, row, hd * DH + d, hi);
            store_elem(a3, 64, row, D + hd * DH + d, lo);
        }
        __syncthreads();
    }
}

// ---------------- launcher ----------------
extern "C" void kernel_launch(void* const* d_in, const int* in_sizes, int n_in,
                              void* d_out, int out_size) {
    const int*   x   = (const int*)  d_in[0];
    const int*   len = (const int*)  d_in[1];
    const float* tok = (const float*)d_in[2];
    const float* pos = (const float*)d_in[3];
    const float* leg = (const float*)d_in[4];
    const float* leb = (const float*)d_in[5];
    const float* Wq = (const float*)d_in[6];  const float* bq = (const float*)d_in[7];
    const float* Wk = (const float*)d_in[8];  const float* bk = (const float*)d_in[9];
    const float* Wv = (const float*)d_in[10]; const float* bv = (const float*)d_in[11];
    const float* Wo = (const float*)d_in[12]; const float* bo = (const float*)d_in[13];
    const float* l1g = (const float*)d_in[14]; const float* l1b = (const float*)d_in[15];
    const float* W1 = (const float*)d_in[16]; const float* b1 = (const float*)d_in[17];
    const float* W2 = (const float*)d_in[18]; const float* b2 = (const float*)d_in[19];
    const float* l2g = (const float*)d_in[20]; const float* l2b = (const float*)d_in[21];
    const float* pW = (const float*)d_in[22]; const float* pb = (const float*)d_in[23];
    float* out = (float*)d_out;

    float *h, *qkv, *tmp, *bqkv;
    __half *a3, *s2, *wqkv, *wo, *w1, *w2, *wp;
    cudaGetSymbolAddress((void**)&h, g_h);     cudaGetSymbolAddress((void**)&qkv, g_qkv);
    cudaGetSymbolAddress((void**)&tmp, g_tmp); cudaGetSymbolAddress((void**)&bqkv, g_bqkv);
    cudaGetSymbolAddress((void**)&a3, g_a3);   cudaGetSymbolAddress((void**)&s2, g_s2);
    cudaGetSymbolAddress((void**)&wqkv, g_wqkv); cudaGetSymbolAddress((void**)&wo, g_wo);
    cudaGetSymbolAddress((void**)&w1, g_w1);   cudaGetSymbolAddress((void**)&w2, g_w2);
    cudaGetSymbolAddress((void**)&wp, g_wp);

    const int smg = NSTG * STG + 128;
    cudaFuncSetAttribute(gemm_kernel, cudaFuncAttributeMaxDynamicSharedMemorySize, smg);
    cudaFuncSetAttribute(attn_kernel, cudaFuncAttributeMaxDynamicSharedMemorySize, ATTN_SMEM);

    // launch order: index 3 (ncu-captured) is the QKV GEMM
    embed_ln_kernel<<<TOK, 256>>>(x, len, tok, pos, leg, leb, h, a3);          // 0
    convert_qkv<<<dim3(D/32, D/32, 3), 256>>>(Wq, Wk, Wv, wqkv);               // 1
    concat_bias<<<4, 256>>>(bq, bk, bv, bqkv);                                 // 2
    gemm_kernel<<<dim3(TOK/128, K3D/128), 256, smg>>>(                         // 3
        a3, wqkv, bqkv, qkv, (__half*)0, D, K3D, 0, len);

    convert_w<<<dim3(D/32, D/32), 256>>>(Wo, wo, D, D, 0);
    convert_w<<<dim3(D/32, FF/32), 256>>>(W1, w1, D, FF, 0);
    convert_w<<<dim3(FF/32, D/32), 256>>>(W2, w2, FF, D, 0);
    {
        size_t w = (size_t)D * D;
        convert_qkv<<<dim3(D/32, D/32, 3), 256>>>(Wq + w, Wk + w, Wv + w, wqkv + (size_t)K3D * D);
        convert_w<<<dim3(D/32, D/32), 256>>>(Wo + w, wo + (size_t)D*D, D, D, 0);
        convert_w<<<dim3(D/32, FF/32), 256>>>(W1 + (size_t)D*FF, w1 + (size_t)FF*D, D, FF, 0);
        convert_w<<<dim3(FF/32, D/32), 256>>>(W2 + (size_t)FF*D, w2 + (size_t)D*FF, FF, D, 0);
        concat_bias<<<4, 256>>>(bq + D, bk + D, bv + D, bqkv + K3D);
    }
    convert_w<<<dim3(D/32, V/32), 256>>>(pW, wp, D, V, 0);

    for (int i = 0; i < LYRS; i++) {
        if (i > 0)
            gemm_kernel<<<dim3(TOK/128, K3D/128), 256, smg>>>(
                a3, wqkv + (size_t)i*K3D*D, bqkv + (size_t)i*K3D, qkv, (__half*)0, D, K3D, 0, len);

        attn_kernel<<<dim3(SLEN/QT, H, BS), 256, ATTN_SMEM>>>(qkv, a3, len);

        gemm_kernel<<<dim3(TOK/128, D/128), 256, smg>>>(
            a3, wo + (size_t)i*D*D, bo + (size_t)i*D, tmp, (__half*)0, D, D, 0, len);
        add_ln_kernel<<<TOK, 256>>>(h, tmp, l1g + (size_t)i*D, l1b + (size_t)i*D, (const int*)0, h, a3);

        gemm_kernel<<<dim3(TOK/128, FF/128), 256, smg>>>(
            a3, w1 + (size_t)i*FF*D, b1 + (size_t)i*FF, (float*)0, s2, D, FF, 1, len);

        gemm_kernel<<<dim3(TOK/128, D/128), 256, smg>>>(
            s2, w2 + (size_t)i*D*FF, b2 + (size_t)i*D, tmp, (__half*)0, FF, D, 0, len);
        add_ln_kernel<<<TOK, 256>>>(h, tmp, l2g + (size_t)i*D, l2b + (size_t)i*D, len, h, a3);
    }

    gemm_kernel<<<dim3(TOK/128, V/128), 256, smg>>>(
        a3, wp, pb, out, (__half*)0, D, V, 0, len);
}

// round 17
// speedup vs baseline: 1.8602x; 1.1758x over previous
#include <cuda_runtime.h>
#include <cuda_fp16.h>
#include <math.h>
#include <stdint.h>

#define LYRS 2
#define H 16
#define D 1024
#define DH 64
#define FF 4096
#define V 32000
#define SLEN 1024
#define BS 2
#define TOK (BS*SLEN)
#define EPS 1e-12f
#define K3D (3*D)

// ---------------- scratch ----------------
__device__ float g_h  [TOK*D];
__device__ float g_qkv[TOK*K3D];
__device__ float g_tmp[TOK*D];
__device__ float g_bqkv[LYRS*K3D];
__device__ __align__(256) __half g_a3 [TOK*2*D];
__device__ __align__(256) __half g_s2 [TOK*2*FF];
__device__ __align__(256) __half g_wqkv[LYRS*(size_t)K3D*D];
__device__ __align__(256) __half g_wo  [LYRS*(size_t)D*D];
__device__ __align__(256) __half g_w1  [LYRS*(size_t)FF*D];
__device__ __align__(256) __half g_w2  [LYRS*(size_t)D*FF];
__device__ __align__(256) __half g_wp  [(size_t)V*D];

// ---------------- helpers ----------------
__device__ __forceinline__ uint32_t s2u(const void* p) {
    uint32_t a;
    asm("{ .reg .u64 t; cvta.to.shared.u64 t, %1; cvt.u32.u64 %0, t; }" : "=r"(a) : "l"(p));
    return a;
}
#define SWZ32(o) ((o) ^ (((o) >> 3) & 0x30))
__device__ __forceinline__ void mbar_init(uint32_t a, uint32_t c) {
    asm volatile("mbarrier.init.shared.b64 [%0], %1;" :: "r"(a), "r"(c) : "memory");
}
__device__ __forceinline__ void mbar_expect(uint32_t a, uint32_t tx) {
    asm volatile("mbarrier.arrive.expect_tx.shared.b64 _, [%0], %1;" :: "r"(a), "r"(tx) : "memory");
}
__device__ __forceinline__ void mbar_arrive(uint32_t a) {
    asm volatile("mbarrier.arrive.shared.b64 _, [%0];" :: "r"(a) : "memory");
}
__device__ __forceinline__ void mbar_wait(uint32_t a, uint32_t ph) {
    asm volatile(
        "{\n\t.reg .pred P;\n\tL_%=:\n\t"
        "mbarrier.try_wait.parity.acquire.cta.shared::cta.b64 P, [%0], %1, 0x989680;\n\t"
        "@P bra D_%=;\n\tbra L_%=;\n\tD_%=:\n\t}" :: "r"(a), "r"(ph) : "memory");
}
__device__ __forceinline__ void bulk_ld(uint32_t dst, const void* src, uint32_t bytes, uint32_t mbar) {
    asm volatile("cp.async.bulk.shared::cta.global.mbarrier::complete_tx::bytes [%0], [%1], %2, [%3];"
                 :: "r"(dst), "l"(src), "r"(bytes), "r"(mbar) : "memory");
}
__device__ __forceinline__ void ldm4(uint32_t (&r)[4], uint32_t addr) {
    asm volatile("ldmatrix.sync.aligned.m8n8.x4.shared.b16 {%0,%1,%2,%3}, [%4];"
                 : "=r"(r[0]), "=r"(r[1]), "=r"(r[2]), "=r"(r[3]) : "r"(addr));
}
__device__ __forceinline__ void mma16816(float (&c)[4], const uint32_t a0, const uint32_t a1,
                                         const uint32_t a2, const uint32_t a3,
                                         const uint32_t b0, const uint32_t b1) {
    asm volatile("mma.sync.aligned.m16n8k16.row.col.f32.f16.f16.f32 "
                 "{%0,%1,%2,%3}, {%4,%5,%6,%7}, {%8,%9}, {%0,%1,%2,%3};"
                 : "+f"(c[0]), "+f"(c[1]), "+f"(c[2]), "+f"(c[3])
                 : "r"(a0), "r"(a1), "r"(a2), "r"(a3), "r"(b0), "r"(b1));
}
__device__ __forceinline__ void split2(float v, __half& hi, __half& lo) {
    hi = __float2half(v);
    lo = __float2half(v - __half2float(hi));
}
__device__ __forceinline__ void store_elem(__half* buf, int nch, int row, int k, __half v) {
    int t = row >> 7, rr = row & 127, c = k >> 5, kk = k & 31;
    uint32_t off = SWZ32((uint32_t)(rr * 64 + kk * 2));
    *(__half*)((char*)buf + (((size_t)(t * nch + c)) << 13) + off) = v;
}

// ---------------- weight conversion ----------------
__device__ __forceinline__ void conv_tile(const float* __restrict__ W, __half* __restrict__ out,
                                          int N, int nch, int k0, int n0, int rowOff) {
    __shared__ float t[32][33];
    __shared__ __half hb[32][40];
    int tx = threadIdx.x & 31, ty = threadIdx.x >> 5;
    #pragma unroll
    for (int i = 0; i < 4; i++)
        t[ty + i * 8][tx] = W[(size_t)(k0 + ty + i * 8) * N + n0 + tx];
    __syncthreads();
    #pragma unroll
    for (int i = 0; i < 4; i++)
        hb[ty + i * 8][tx] = __float2half(t[tx][ty + i * 8]);
    __syncthreads();
    if (threadIdx.x < 128) {
        int r = threadIdx.x >> 2, slot = threadIdx.x & 3;
        int n = rowOff + n0 + r;
        int tt = n >> 7, rr = n & 127;
        int sl = slot ^ ((rr >> 1) & 3);
        int4 v = *(int4*)&hb[r][slot * 8];
        *(int4*)((char*)out + (((size_t)(tt * nch + (k0 >> 5))) << 13) + rr * 64 + sl * 16) = v;
    }
}
__global__ void convert_w(const float* __restrict__ W, __half* __restrict__ out,
                          int K, int N, int rowOff) {
    conv_tile(W, out, N, K >> 5, blockIdx.x * 32, blockIdx.y * 32, rowOff);
}
__global__ void convert_qkv(const float* __restrict__ Wq, const float* __restrict__ Wk,
                            const float* __restrict__ Wv, __half* __restrict__ out) {
    const float* W = (blockIdx.z == 0) ? Wq : (blockIdx.z == 1) ? Wk : Wv;
    conv_tile(W, out, D, D >> 5, blockIdx.x * 32, blockIdx.y * 32, blockIdx.z * D);
}
__global__ void concat_bias(const float* __restrict__ a, const float* __restrict__ b,
                            const float* __restrict__ c, float* __restrict__ o) {
    int i = blockIdx.x * 256 + threadIdx.x;
    if (i < D) { o[i] = a[i]; o[D + i] = b[i]; o[2 * D + i] = c[i]; }
}

// ---------------- GEMM: NPH fp16 phases (A=[hi(|lo)]), ring depth NST ----------------
template<int NPH, int NST>
__global__ void __launch_bounds__(256, 2) gemm_kernel(
    const __half* __restrict__ A, const __half* __restrict__ B,
    const float* __restrict__ bias, float* __restrict__ C, __half* __restrict__ S,
    int Kp, int N, int act, const int* __restrict__ lenp)
{
    constexpr int STG = (NPH + 1) * 8192;
    extern __shared__ __align__(128) char smem[];
    const int tid = threadIdx.x, wid = tid >> 5, lane = tid & 31;
    const int wm = wid & 3, wn = wid >> 2;
    const int m0 = blockIdx.x * 128, n0 = blockIdx.y * 128;

    if (lenp && (m0 & 1023) >= lenp[m0 >> 10]) {
        if (C) {
            for (int idx = tid; idx < 128 * 32; idx += 256) {
                int r = idx >> 5, c4 = (idx & 31) * 4;
                float4 bv = *(const float4*)(bias + n0 + c4);
                *(float4*)(C + (size_t)(m0 + r) * N + n0 + c4) = bv;
            }
        }
        return;
    }

    const uint32_t sb = s2u(smem);
    const uint32_t FB = sb + NST * STG;
    const uint32_t EB = FB + NST * 8;
    const int nch0 = Kp / 32;

    if (tid == 0) {
        #pragma unroll
        for (int s = 0; s < NST; s++) { mbar_init(FB + 8 * s, 1); mbar_init(EB + 8 * s, 8); }
    }
    __syncthreads();

    auto issue = [&](int kk) {
        int s = kk % NST;
        uint32_t mb = FB + 8 * s, dst = sb + s * STG;
        mbar_expect(mb, (NPH + 1) * 8192);
        bulk_ld(dst, (const char*)A + (((size_t)(blockIdx.x * 2 * nch0 + kk)) << 13), 8192, mb);
        if (NPH == 2)
            bulk_ld(dst + 8192, (const char*)A + (((size_t)(blockIdx.x * 2 * nch0 + nch0 + kk)) << 13), 8192, mb);
        bulk_ld(dst + NPH * 8192, (const char*)B + (((size_t)(blockIdx.y * nch0 + kk)) << 13), 8192, mb);
    };
    if (tid == 0) {
        #pragma unroll
        for (int s = 0; s < NST - 1; s++) if (s < nch0) issue(s);
    }

    float acc[2][8][4];
    #pragma unroll
    for (int mi = 0; mi < 2; mi++)
        #pragma unroll
        for (int ni = 0; ni < 8; ni++)
            #pragma unroll
            for (int j = 0; j < 4; j++) acc[mi][ni][j] = 0.f;

    const int lq = lane & 7, lh = (lane >> 3) & 1, lk = lane >> 4;

    for (int kk = 0; kk < nch0; kk++) {
        int s = kk % NST;
        mbar_wait(FB + 8 * s, (kk / NST) & 1);
        uint32_t stg = sb + s * STG;
        uint32_t bstg = stg + NPH * 8192;
        #pragma unroll
        for (int p = 0; p < NPH; p++) {
            uint32_t astg = stg + p * 8192;
            #pragma unroll
            for (int ks = 0; ks < 2; ks++) {
                uint32_t af[2][4], bf[4][4];
                #pragma unroll
                for (int mt = 0; mt < 2; mt++) {
                    int r = wm * 32 + mt * 16 + lh * 8 + lq;
                    int sl = (ks * 2 + lk) ^ ((r >> 1) & 3);
                    ldm4(af[mt], astg + r * 64 + (sl << 4));
                }
                #pragma unroll
                for (int nt = 0; nt < 4; nt++) {
                    int r = wn * 64 + nt * 16 + lh * 8 + lq;
                    int sl = (ks * 2 + lk) ^ ((r >> 1) & 3);
                    ldm4(bf[nt], bstg + r * 64 + (sl << 4));
                }
                #pragma unroll
                for (int mi = 0; mi < 2; mi++)
                    #pragma unroll
                    for (int ni = 0; ni < 8; ni++) {
                        uint32_t b0 = bf[ni >> 1][ni & 1], b1 = bf[ni >> 1][(ni & 1) + 2];
                        mma16816(acc[mi][ni], af[mi][0], af[mi][1], af[mi][2], af[mi][3], b0, b1);
                    }
            }
        }
        if (lane == 0) mbar_arrive(EB + 8 * s);
        if (tid == 0) {
            int cc = kk + NST - 1;
            if (cc < nch0) {
                if (cc >= NST) mbar_wait(EB + 8 * (cc % NST), ((cc / NST) + 1) & 1);
                issue(cc);
            }
        }
    }

    const int r0 = lane >> 2, cp = (lane & 3) * 2;
    const int nchS = N >> 4;
    #pragma unroll
    for (int mi = 0; mi < 2; mi++) {
        #pragma unroll
        for (int ni = 0; ni < 8; ni++) {
            int col = n0 + wn * 64 + ni * 8 + cp;
            float bb0 = bias[col], bb1 = bias[col + 1];
            #pragma unroll
            for (int half = 0; half < 2; half++) {
                int row = m0 + wm * 32 + mi * 16 + r0 + half * 8;
                float v0 = acc[mi][ni][half * 2 + 0] + bb0;
                float v1 = acc[mi][ni][half * 2 + 1] + bb1;
                if (act) {
                    v0 = 0.5f * v0 * (1.0f + erff(v0 * 0.70710678118654752f));
                    v1 = 0.5f * v1 * (1.0f + erff(v1 * 0.70710678118654752f));
                }
                if (C) {
                    float2 o; o.x = v0; o.y = v1;
                    *(float2*)(C + (size_t)row * N + col) = o;
                }
                if (S) {
                    __half h0, l0, h1, l1;
                    split2(v0, h0, l0); split2(v1, h1, l1);
                    int t = row >> 7, rr = row & 127;
                    uint32_t off = SWZ32((uint32_t)(rr * 64 + (col & 31) * 2));
                    __half2 hp; hp.x = h0; hp.y = h1;
                    *(__half2*)((char*)S + (((size_t)(t * nchS + (col >> 5))) << 13) + off) = hp;
                    __half2 lp; lp.x = l0; lp.y = l1;
                    *(__half2*)((char*)S + (((size_t)(t * nchS + ((N + col) >> 5))) << 13) + off) = lp;
                }
            }
        }
    }
}

// ---------------- LayerNorm ----------------
__device__ __forceinline__ float brsum(float v, float* sbuf) {
    int tid = threadIdx.x;
    #pragma unroll
    for (int o = 16; o; o >>= 1) v += __shfl_down_sync(0xffffffffu, v, o);
    if ((tid & 31) == 0) sbuf[tid >> 5] = v;
    __syncthreads();
    if (tid < 8) {
        v = sbuf[tid];
        #pragma unroll
        for (int o = 4; o; o >>= 1) v += __shfl_down_sync(0xffu, v, o);
        if (tid == 0) sbuf[0] = v;
    }
    __syncthreads();
    float r = sbuf[0];
    __syncthreads();
    return r;
}
__device__ __forceinline__ void ln_zero_row(float* out, __half* sp, int row, int tid) {
    #pragma unroll
    for (int i = 0; i < 4; i++) {
        int c = tid + i * 256;
        out[(size_t)row * D + c] = 0.f;
        store_elem(sp, 64, row, c, __float2half(0.f));
        store_elem(sp, 64, row, D + c, __float2half(0.f));
    }
}
__global__ void embed_ln_kernel(const int* __restrict__ x, const int* __restrict__ len,
                                const float* __restrict__ tok, const float* __restrict__ pos,
                                const float* __restrict__ g, const float* __restrict__ b,
                                float* __restrict__ out, __half* __restrict__ sp) {
    int row = blockIdx.x, bi = row / SLEN, s = row % SLEN, tid = threadIdx.x;
    if (s >= len[bi]) { ln_zero_row(out, sp, row, tid); return; }
    int token = x[row];
    __shared__ float buf[D]; __shared__ float red[8];
    float ls = 0.f;
    #pragma unroll
    for (int i = 0; i < 4; i++) {
        int c = tid + i * 256;
        float v = tok[(size_t)token * D + c] + pos[(size_t)s * D + c];
        buf[c] = v; ls += v;
    }
    float mean = brsum(ls, red) * (1.0f / D), ss = 0.f;
    #pragma unroll
    for (int i = 0; i < 4; i++) { float d = buf[tid + i * 256] - mean; ss += d * d; }
    float rstd = rsqrtf(brsum(ss, red) * (1.0f / D) + EPS);
    #pragma unroll
    for (int i = 0; i < 4; i++) {
        int c = tid + i * 256;
        float v = g[c] * (buf[c] - mean) * rstd + b[c];
        out[(size_t)row * D + c] = v;
        __half hi, lo; split2(v, hi, lo);
        store_elem(sp, 64, row, c, hi);
        store_elem(sp, 64, row, D + c, lo);
    }
}
__global__ void add_ln_kernel(const float* __restrict__ a, const float* __restrict__ dl,
                              const float* __restrict__ g, const float* __restrict__ b,
                              const int* __restrict__ len, float* __restrict__ out,
                              __half* __restrict__ sp) {
    int row = blockIdx.x, bi = row / SLEN, s = row % SLEN, tid = threadIdx.x;
    if (len && s >= len[bi]) { ln_zero_row(out, sp, row, tid); return; }
    __shared__ float buf[D]; __shared__ float red[8];
    float ls = 0.f;
    #pragma unroll
    for (int i = 0; i < 4; i++) {
        int c = tid + i * 256;
        float v = a[(size_t)row * D + c] + dl[(size_t)row * D + c];
        buf[c] = v; ls += v;
    }
    float mean = brsum(ls, red) * (1.0f / D), ss = 0.f;
    #pragma unroll
    for (int i = 0; i < 4; i++) { float d = buf[tid + i * 256] - mean; ss += d * d; }
    float rstd = rsqrtf(brsum(ss, red) * (1.0f / D) + EPS);
    #pragma unroll
    for (int i = 0; i < 4; i++) {
        int c = tid + i * 256;
        float v = g[c] * (buf[c] - mean) * rstd + b[c];
        out[(size_t)row * D + c] = v;
        __half hi, lo; split2(v, hi, lo);
        store_elem(sp, 64, row, c, hi);
        store_elem(sp, 64, row, D + c, lo);
    }
}

// ---------------- attention: 16 q/block, 256 threads ----------------
#define QT 16
#define KCH 128
#define ATTN_SMEM ((QT*DH + QT*SLEN + KCH*65 + QT) * 4)
__global__ void __launch_bounds__(256) attn_kernel(const float* __restrict__ qkv,
                                                   __half* __restrict__ a3,
                                                   const int* __restrict__ lenp) {
    const int q0 = blockIdx.x * QT, hd = blockIdx.y, bb = blockIdx.z, tid = threadIdx.x;
    if (q0 >= lenp[bb]) return;
    extern __shared__ float sm[];
    float* sq = sm;
    float* sc = sq + QT * DH;
    float* sk = sc + QT * SLEN;
    float* sinv = sk + KCH * 65;
    const int wid = tid >> 5, lane = tid & 31;
    const int nkb = q0 + QT;
    const size_t rb = (size_t)(bb * SLEN) * K3D + (size_t)hd * DH;

    for (int i = tid; i < QT * DH; i += 256)
        sq[i] = qkv[rb + (size_t)(q0 + i / DH) * K3D + (i % DH)] * 0.125f;
    __syncthreads();

    const float* kb = qkv + rb + D;
    for (int c0 = 0; c0 < nkb; c0 += KCH) {
        int rows = nkb - c0; if (rows > KCH) rows = KCH;
        for (int idx = tid; idx < rows * 16; idx += 256) {
            int r = idx >> 4, c4 = (idx & 15) * 4;
            float4 v = *(const float4*)(kb + (size_t)(c0 + r) * K3D + c4);
            sk[r * 65 + c4 + 0] = v.x; sk[r * 65 + c4 + 1] = v.y;
            sk[r * 65 + c4 + 2] = v.z; sk[r * 65 + c4 + 3] = v.w;
        }
        __syncthreads();
        for (int key = tid; key < rows; key += 256) {
            float a[QT];
            #pragma unroll
            for (int qi = 0; qi < QT; qi++) a[qi] = 0.f;
            #pragma unroll 8
            for (int d = 0; d < DH; d++) {
                float kd = sk[key * 65 + d];
                #pragma unroll
                for (int qi = 0; qi < QT; qi++) a[qi] = fmaf(sq[qi * DH + d], kd, a[qi]);
            }
            #pragma unroll
            for (int qi = 0; qi < QT; qi++) sc[qi * SLEN + c0 + key] = a[qi];
        }
        __syncthreads();
    }

    #pragma unroll
    for (int t = 0; t < 2; t++) {
        int qi = wid * 2 + t, bound = q0 + qi;
        float mx = -1e30f;
        for (int key = lane; key <= bound; key += 32) mx = fmaxf(mx, sc[qi * SLEN + key]);
        #pragma unroll
        for (int o = 16; o; o >>= 1) mx = fmaxf(mx, __shfl_xor_sync(0xffffffffu, mx, o));
        float s = 0.f;
        for (int key = lane; key < nkb; key += 32) {
            float e = (key <= bound) ? expf(sc[qi * SLEN + key] - mx) : 0.f;
            sc[qi * SLEN + key] = e; s += e;
        }
        #pragma unroll
        for (int o = 16; o; o >>= 1) s += __shfl_xor_sync(0xffffffffu, s, o);
        if (lane == 0) sinv[qi] = 1.0f / s;
    }
    __syncthreads();

    const int d = tid & 63, q4 = tid >> 6;
    const float* vb = qkv + rb + 2 * D;
    float a[QT];
    #pragma unroll
    for (int qi = 0; qi < QT; qi++) a[qi] = 0.f;
    for (int c0 = 0; c0 < nkb; c0 += KCH) {
        int rows = nkb - c0; if (rows > KCH) rows = KCH;
        for (int idx = tid; idx < rows * 16; idx += 256) {
            int r = idx >> 4, c4 = (idx & 15) * 4;
            float4 v = *(const float4*)(vb + (size_t)(c0 + r) * K3D + c4);
            sk[r * 65 + c4 + 0] = v.x; sk[r * 65 + c4 + 1] = v.y;
            sk[r * 65 + c4 + 2] = v.z; sk[r * 65 + c4 + 3] = v.w;
        }
        __syncthreads();
        for (int key = q4; key < rows; key += 4) {
            float vv = sk[key * 65 + d];
            #pragma unroll
            for (int qi = 0; qi < QT; qi++)
                a[qi] = fmaf(sc[qi * SLEN + c0 + key], vv, a[qi]);
        }
        __syncthreads();
    }
    for (int qi = 0; qi < QT; qi++) {
        sk[tid] = a[qi]; __syncthreads();
        if (tid < 64) {
            float v = (sk[tid] + sk[tid + 64] + sk[tid + 128] + sk[tid + 192]) * sinv[qi];
            int row = bb * SLEN + q0 + qi;
            __half hi, lo; split2(v, hi, lo);
            store_elem(a3, 64, row, hd * DH + d, hi);
            store_elem(a3, 64, row, D + hd * DH + d, lo);
        }
        __syncthreads();
    }
}

// ---------------- launcher ----------------
extern "C" void kernel_launch(void* const* d_in, const int* in_sizes, int n_in,
                              void* d_out, int out_size) {
    const int*   x   = (const int*)  d_in[0];
    const int*   len = (const int*)  d_in[1];
    const float* tok = (const float*)d_in[2];
    const float* pos = (const float*)d_in[3];
    const float* leg = (const float*)d_in[4];
    const float* leb = (const float*)d_in[5];
    const float* Wq = (const float*)d_in[6];  const float* bq = (const float*)d_in[7];
    const float* Wk = (const float*)d_in[8];  const float* bk = (const float*)d_in[9];
    const float* Wv = (const float*)d_in[10]; const float* bv = (const float*)d_in[11];
    const float* Wo = (const float*)d_in[12]; const float* bo = (const float*)d_in[13];
    const float* l1g = (const float*)d_in[14]; const float* l1b = (const float*)d_in[15];
    const float* W1 = (const float*)d_in[16]; const float* b1 = (const float*)d_in[17];
    const float* W2 = (const float*)d_in[18]; const float* b2 = (const float*)d_in[19];
    const float* l2g = (const float*)d_in[20]; const float* l2b = (const float*)d_in[21];
    const float* pW = (const float*)d_in[22]; const float* pb = (const float*)d_in[23];
    float* out = (float*)d_out;

    float *h, *qkv, *tmp, *bqkv;
    __half *a3, *s2, *wqkv, *wo, *w1, *w2, *wp;
    cudaGetSymbolAddress((void**)&h, g_h);     cudaGetSymbolAddress((void**)&qkv, g_qkv);
    cudaGetSymbolAddress((void**)&tmp, g_tmp); cudaGetSymbolAddress((void**)&bqkv, g_bqkv);
    cudaGetSymbolAddress((void**)&a3, g_a3);   cudaGetSymbolAddress((void**)&s2, g_s2);
    cudaGetSymbolAddress((void**)&wqkv, g_wqkv); cudaGetSymbolAddress((void**)&wo, g_wo);
    cudaGetSymbolAddress((void**)&w1, g_w1);   cudaGetSymbolAddress((void**)&w2, g_w2);
    cudaGetSymbolAddress((void**)&wp, g_wp);

    const int smg2 = 4 * 3 * 8192 + 128;   // <2,4>
    const int smg1 = 6 * 2 * 8192 + 128;   // <1,6>
    cudaFuncSetAttribute(gemm_kernel<2,4>, cudaFuncAttributeMaxDynamicSharedMemorySize, smg2);
    cudaFuncSetAttribute(gemm_kernel<1,6>, cudaFuncAttributeMaxDynamicSharedMemorySize, smg1);
    cudaFuncSetAttribute(attn_kernel, cudaFuncAttributeMaxDynamicSharedMemorySize, ATTN_SMEM);

    // launch order: index 3 (ncu-captured) is the QKV GEMM
    embed_ln_kernel<<<TOK, 256>>>(x, len, tok, pos, leg, leb, h, a3);          // 0
    convert_qkv<<<dim3(D/32, D/32, 3), 256>>>(Wq, Wk, Wv, wqkv);               // 1
    concat_bias<<<4, 256>>>(bq, bk, bv, bqkv);                                 // 2
    gemm_kernel<2,4><<<dim3(TOK/128, K3D/128), 256, smg2>>>(                   // 3
        a3, wqkv, bqkv, qkv, (__half*)0, D, K3D, 0, len);

    convert_w<<<dim3(D/32, D/32), 256>>>(Wo, wo, D, D, 0);
    convert_w<<<dim3(D/32, FF/32), 256>>>(W1, w1, D, FF, 0);
    convert_w<<<dim3(FF/32, D/32), 256>>>(W2, w2, FF, D, 0);
    {
        size_t w = (size_t)D * D;
        convert_qkv<<<dim3(D/32, D/32, 3), 256>>>(Wq + w, Wk + w, Wv + w, wqkv + (size_t)K3D * D);
        convert_w<<<dim3(D/32, D/32), 256>>>(Wo + w, wo + (size_t)D*D, D, D, 0);
        convert_w<<<dim3(D/32, FF/32), 256>>>(W1 + (size_t)D*FF, w1 + (size_t)FF*D, D, FF, 0);
        convert_w<<<dim3(FF/32, D/32), 256>>>(W2 + (size_t)FF*D, w2 + (size_t)D*FF, FF, D, 0);
        concat_bias<<<4, 256>>>(bq + D, bk + D, bv + D, bqkv + K3D);
    }
    convert_w<<<dim3(D/32, V/32), 256>>>(pW, wp, D, V, 0);

    for (int i = 0; i < LYRS; i++) {
        if (i > 0)
            gemm_kernel<2,4><<<dim3(TOK/128, K3D/128), 256, smg2>>>(
                a3, wqkv + (size_t)i*K3D*D, bqkv + (size_t)i*K3D, qkv, (__half*)0, D, K3D, 0, len);

        attn_kernel<<<dim3(SLEN/QT, H, BS), 256, ATTN_SMEM>>>(qkv, a3, len);

        gemm_kernel<2,4><<<dim3(TOK/128, D/128), 256, smg2>>>(
            a3, wo + (size_t)i*D*D, bo + (size_t)i*D, tmp, (__half*)0, D, D, 0, len);
        add_ln_kernel<<<TOK, 256>>>(h, tmp, l1g + (size_t)i*D, l1b + (size_t)i*D, (const int*)0, h, a3);

        gemm_kernel<2,4><<<dim3(TOK/128, FF/128), 256, smg2>>>(
            a3, w1 + (size_t)i*FF*D, b1 + (size_t)i*FF, (float*)0, s2, D, FF, 1, len);

        gemm_kernel<2,4><<<dim3(TOK/128, D/128), 256, smg2>>>(
            s2, w2 + (size_t)i*D*FF, b2 + (size_t)i*D, tmp, (__half*)0, FF, D, 0, len);
        add_ln_kernel<<<TOK, 256>>>(h, tmp, l2g + (size_t)i*D, l2b + (size_t)i*D, len, h, a3);
    }

    // final vocab projection: single-phase fp16 (A_lo dropped), deeper ring
    gemm_kernel<1,6><<<dim3(TOK/128, V/128), 256, smg1>>>(
        a3, wp, pb, out, (__half*)0, D, V, 0, len);
}